// round 1
// baseline (speedup 1.0000x reference)
#include <cuda_runtime.h>

#define B_SZ  4
#define N_SEQ 2048
#define DIM   512
#define NH    8
#define DK    64
#define M_ROWS (B_SZ * N_SEQ)
#define SCALE 0.125f

// Scratch for projected Q (scaled + biased) and K, layout [b, n, h*dk] (same as x).
__device__ float g_Q[M_ROWS * DIM];
__device__ float g_K[M_ROWS * DIM];

// ---------------------------------------------------------------------------
// Projection GEMM: out = x @ W  (+ scale/bias epilogue for Q branch)
// M=8192, N=512, K=512. 64x64 block tile, 16 K-tile, 256 threads, 4x4 micro.
// grid.z = 0 -> Q (scale+bias), 1 -> K
// ---------------------------------------------------------------------------
__global__ __launch_bounds__(256) void proj_kernel(
    const float* __restrict__ x, const float* __restrict__ Wq,
    const float* __restrict__ Wk, const float* __restrict__ bias)
{
    const int which = blockIdx.z;
    const float* W = which ? Wk : Wq;
    float* out = which ? g_K : g_Q;

    __shared__ float As[16][68];   // x^T tile, padded (transposed writes)
    __shared__ float Bs[16][64];   // W tile, natural

    const int tid = threadIdx.x;
    const int ty = tid >> 4, tx = tid & 15;
    const int row0 = blockIdx.y * 64;
    const int col0 = blockIdx.x * 64;

    const int ar = tid >> 2;           // 0..63
    const int ac = (tid & 3) << 2;     // 0,4,8,12
    const int br = tid >> 4;           // 0..15
    const int bc = (tid & 15) << 2;    // 0..60

    float acc[4][4] = {};

    for (int k0 = 0; k0 < DIM; k0 += 16) {
        float4 av = *reinterpret_cast<const float4*>(
            &x[(size_t)(row0 + ar) * DIM + k0 + ac]);
        As[ac + 0][ar] = av.x;
        As[ac + 1][ar] = av.y;
        As[ac + 2][ar] = av.z;
        As[ac + 3][ar] = av.w;
        *reinterpret_cast<float4*>(&Bs[br][bc]) =
            *reinterpret_cast<const float4*>(&W[(size_t)(k0 + br) * DIM + col0 + bc]);
        __syncthreads();
#pragma unroll
        for (int kk = 0; kk < 16; kk++) {
            float a[4], b[4];
#pragma unroll
            for (int r = 0; r < 4; r++) a[r] = As[kk][ty * 4 + r];
#pragma unroll
            for (int c = 0; c < 4; c++) b[c] = Bs[kk][tx * 4 + c];
#pragma unroll
            for (int r = 0; r < 4; r++)
#pragma unroll
                for (int c = 0; c < 4; c++) acc[r][c] += a[r] * b[c];
        }
        __syncthreads();
    }

#pragma unroll
    for (int r = 0; r < 4; r++) {
        const int row = row0 + ty * 4 + r;
#pragma unroll
        for (int c = 0; c < 4; c++) {
            const int col = col0 + tx * 4 + c;
            float v = acc[r][c];
            if (which == 0) v = v * SCALE + bias[col];   // q*SCALE + rel_content_bias
            out[(size_t)row * DIM + col] = v;
        }
    }
}

// ---------------------------------------------------------------------------
// Fused sigmoid attention: per (b, h, 64-row Q tile), stream over 64-key tiles:
//   S = Q Kt ;  P = sigmoid(S) ;  O += P V     (V = head-slice of x)
// smem: Qs[64][65] (d-major), KP[64][65] (K d-major, then P key-major), Vs[64][64]
// 256 threads, 4x4 micro-tiles for both GEMM phases.
// ---------------------------------------------------------------------------
__global__ __launch_bounds__(256) void attn_kernel(
    const float* __restrict__ x, float* __restrict__ out)
{
    extern __shared__ float smem[];
    float* Qs = smem;                 // [64][65]  Qs[d*65 + i]
    float* KP = smem + 64 * 65;       // [64][65]  K: KP[d*65 + j]; P: KP[key*65 + i]
    float* Vs = smem + 2 * 64 * 65;   // [64][64]  Vs[key*64 + d]

    const int it = blockIdx.x, h = blockIdx.y, b = blockIdx.z;
    const int tid = threadIdx.x;
    const int ty = tid >> 4, tx = tid & 15;
    const int i0 = ty * 4, j0 = tx * 4;

    const size_t base = (size_t)b * N_SEQ * DIM + (size_t)h * DK;
    const float* qg = g_Q + base + (size_t)(it * 64) * DIM;
    const float* kg = g_K + base;
    const float* vg = x + base;

    const int lr = tid >> 4;          // 0..15
    const int lc = (tid & 15) << 2;   // 0..60

    // Load Q tile transposed (d-major), padded rows -> conflict-free writes
#pragma unroll
    for (int p = 0; p < 4; p++) {
        const int row = p * 16 + lr;
        float4 v = *reinterpret_cast<const float4*>(&qg[(size_t)row * DIM + lc]);
        Qs[(lc + 0) * 65 + row] = v.x;
        Qs[(lc + 1) * 65 + row] = v.y;
        Qs[(lc + 2) * 65 + row] = v.z;
        Qs[(lc + 3) * 65 + row] = v.w;
    }

    float O[4][4] = {};

    for (int jt = 0; jt < N_SEQ / 64; jt++) {
        __syncthreads();   // protects KP/Vs reuse from previous iter (and Q on iter 0)
        const float* kt = kg + (size_t)(jt * 64) * DIM;
        const float* vt = vg + (size_t)(jt * 64) * DIM;
#pragma unroll
        for (int p = 0; p < 4; p++) {
            const int row = p * 16 + lr;
            float4 v = *reinterpret_cast<const float4*>(&kt[(size_t)row * DIM + lc]);
            KP[(lc + 0) * 65 + row] = v.x;
            KP[(lc + 1) * 65 + row] = v.y;
            KP[(lc + 2) * 65 + row] = v.z;
            KP[(lc + 3) * 65 + row] = v.w;
            float4 w = *reinterpret_cast<const float4*>(&vt[(size_t)row * DIM + lc]);
            *reinterpret_cast<float4*>(&Vs[row * 64 + lc]) = w;
        }
        __syncthreads();

        // S = Q K^T over dk=64
        float S[4][4] = {};
#pragma unroll 8
        for (int kk = 0; kk < 64; kk++) {
            float a[4], bb[4];
#pragma unroll
            for (int r = 0; r < 4; r++) a[r] = Qs[kk * 65 + i0 + r];
#pragma unroll
            for (int c = 0; c < 4; c++) bb[c] = KP[kk * 65 + j0 + c];
#pragma unroll
            for (int r = 0; r < 4; r++)
#pragma unroll
                for (int c = 0; c < 4; c++) S[r][c] += a[r] * bb[c];
        }
        __syncthreads();   // everyone done reading KP as K

        // P = sigmoid(S), stored key-major into KP
#pragma unroll
        for (int c = 0; c < 4; c++)
#pragma unroll
            for (int r = 0; r < 4; r++)
                KP[(j0 + c) * 65 + (i0 + r)] = 1.0f / (1.0f + expf(-S[r][c]));
        __syncthreads();

        // O += P V over 64 keys
#pragma unroll 8
        for (int kk = 0; kk < 64; kk++) {
            float p[4], v[4];
#pragma unroll
            for (int r = 0; r < 4; r++) p[r] = KP[kk * 65 + i0 + r];
#pragma unroll
            for (int c = 0; c < 4; c++) v[c] = Vs[kk * 64 + j0 + c];
#pragma unroll
            for (int r = 0; r < 4; r++)
#pragma unroll
                for (int c = 0; c < 4; c++) O[r][c] += p[r] * v[c];
        }
    }

    float* og = out + (size_t)b * N_SEQ * DIM + (size_t)(it * 64) * DIM + (size_t)h * DK;
#pragma unroll
    for (int r = 0; r < 4; r++) {
        float4 v = make_float4(O[r][0], O[r][1], O[r][2], O[r][3]);
        *reinterpret_cast<float4*>(&og[(size_t)(i0 + r) * DIM + j0]) = v;
    }
}

extern "C" void kernel_launch(void* const* d_in, const int* in_sizes, int n_in,
                              void* d_out, int out_size)
{
    const float* x    = (const float*)d_in[0];
    const float* Wq   = (const float*)d_in[1];
    const float* Wk   = (const float*)d_in[2];
    const float* bias = (const float*)d_in[3];  // rel_content_bias, H*DK = 512 floats
    float* out = (float*)d_out;

    // 49,664 B dynamic smem > 48K default; attribute is per-function persistent
    // state set on the pre-capture correctness call as well, so capture is safe.
    cudaFuncSetAttribute(attn_kernel, cudaFuncAttributeMaxDynamicSharedMemorySize, 49664);

    proj_kernel<<<dim3(DIM / 64, M_ROWS / 64, 2), 256>>>(x, Wq, Wk, bias);
    attn_kernel<<<dim3(N_SEQ / 64, NH, B_SZ), 256, 49664>>>(x, out);
}

// round 3
// speedup vs baseline: 3.1972x; 3.1972x over previous
#include <cuda_runtime.h>
#include <cstdint>

#define B_SZ  4
#define N_SEQ 2048
#define DIM   512
#define NH    8
#define DK    64
#define M_ROWS (B_SZ * N_SEQ)
#define SCALE 0.125f

// Scratch for projected Q (scaled + biased, tf32-rounded) and K (tf32-rounded).
__device__ float g_Q[M_ROWS * DIM];
__device__ float g_K[M_ROWS * DIM];

// ---------------------------------------------------------------------------
// helpers (portable PTX only: sm_80+ features, nothing arch-"a"-specific)
// ---------------------------------------------------------------------------
__device__ __forceinline__ float tf32r(float x) {
    float y;
    asm("cvt.rna.tf32.f32 %0, %1;" : "=f"(y) : "f"(x));
    return y;
}
__device__ __forceinline__ uint32_t su32(const void* p) {
    uint32_t a;
    asm("{ .reg .u64 t; cvta.to.shared.u64 t, %1; cvt.u32.u64 %0, t; }" : "=r"(a) : "l"(p));
    return a;
}
#define CPA(sa, gp) asm volatile("cp.async.cg.shared.global [%0], [%1], 16;" :: "r"(sa), "l"(gp))
#define CPC()  asm volatile("cp.async.commit_group;" ::: "memory")
#define CPW(n) asm volatile("cp.async.wait_group %0;" :: "n"(n) : "memory")

// D(16x8,f32) += A(16x8,tf32 row) * B(8x8,tf32 col)
__device__ __forceinline__ void mma8(float* d, const uint32_t* a, uint32_t b0, uint32_t b1) {
    asm volatile(
        "mma.sync.aligned.m16n8k8.row.col.f32.tf32.tf32.f32 "
        "{%0,%1,%2,%3}, {%4,%5,%6,%7}, {%8,%9}, {%0,%1,%2,%3};"
        : "+f"(d[0]), "+f"(d[1]), "+f"(d[2]), "+f"(d[3])
        : "r"(a[0]), "r"(a[1]), "r"(a[2]), "r"(a[3]), "r"(b0), "r"(b1));
}

__device__ __forceinline__ float sigf(float x) {
    float e, r;
    asm("ex2.approx.f32 %0, %1;" : "=f"(e) : "f"(-1.4426950408889634f * x));
    asm("rcp.approx.f32 %0, %1;" : "=f"(r) : "f"(1.0f + e));
    return r;
}

// ---------------------------------------------------------------------------
// Projection: g_Q = tf32(x@Wq*SCALE + bias), g_K = tf32(x@Wk)  via tf32 mma
// CTA tile 128(M) x 128(N), k-tile 32, 256 threads (8 warps, 4x2), cp.async 2-stage
// ---------------------------------------------------------------------------
#define PJ_AS 36
#define PJ_BS 136
#define PJ_A_SZ (128 * PJ_AS)   // 4608 floats
#define PJ_B_SZ (32 * PJ_BS)    // 4352 floats
#define PJ_SMEM ((2 * PJ_A_SZ + 2 * PJ_B_SZ) * 4)   // 71,680 B

__global__ __launch_bounds__(256) void proj_tc(
    const float* __restrict__ x, const float* __restrict__ Wq,
    const float* __restrict__ Wk, const float* __restrict__ bias)
{
    extern __shared__ float sm[];
    float* As = sm;                 // 2 x [128][36]
    float* Bs = sm + 2 * PJ_A_SZ;   // 2 x [32][136]
    const uint32_t sb = su32(sm);

    const int which = blockIdx.z;
    const float* W = which ? Wk : Wq;
    float* outp = which ? g_K : g_Q;

    const int tid = threadIdx.x;
    const int wid = tid >> 5, lane = tid & 31;
    const int g = lane >> 2, t = lane & 3;
    const int rg = wid >> 1, cg = wid & 1;
    const int row0 = blockIdx.y * 128, col0 = blockIdx.x * 128;

    #define PJ_LOAD(kt, buf) do {                                               \
        const float* _sa = x + (size_t)row0 * DIM + (kt) * 32;                  \
        uint32_t _da = sb + (uint32_t)((buf) * PJ_A_SZ) * 4u;                   \
        _Pragma("unroll")                                                       \
        for (int i = 0; i < 4; i++) {                                           \
            int c = tid + i * 256, r = c >> 3, c4 = (c & 7) << 2;               \
            CPA(_da + (uint32_t)(r * PJ_AS + c4) * 4u, _sa + (size_t)r * DIM + c4); \
        }                                                                       \
        const float* _sbp = W + (size_t)((kt) * 32) * DIM + col0;               \
        uint32_t _db = sb + (uint32_t)(2 * PJ_A_SZ + (buf) * PJ_B_SZ) * 4u;     \
        _Pragma("unroll")                                                       \
        for (int i = 0; i < 4; i++) {                                           \
            int c = tid + i * 256, r = c >> 5, c4 = (c & 31) << 2;              \
            CPA(_db + (uint32_t)(r * PJ_BS + c4) * 4u, _sbp + (size_t)r * DIM + c4); \
        }                                                                       \
        CPC();                                                                  \
    } while (0)

    float C[2][8][4] = {};

    PJ_LOAD(0, 0);
    for (int kt = 0; kt < 16; kt++) {
        const int buf = kt & 1;
        if (kt < 15) { PJ_LOAD(kt + 1, buf ^ 1); CPW(1); } else { CPW(0); }
        __syncthreads();
        const float* A  = As + buf * PJ_A_SZ;
        const float* Bm = Bs + buf * PJ_B_SZ;
#pragma unroll
        for (int kb = 0; kb < 4; kb++) {
            const int k = kb * 8;
            uint32_t a[2][4];
#pragma unroll
            for (int f = 0; f < 2; f++) {
                const int r = rg * 32 + f * 16 + g;
                a[f][0] = __float_as_uint(tf32r(A[r * PJ_AS + k + t]));
                a[f][1] = __float_as_uint(tf32r(A[(r + 8) * PJ_AS + k + t]));
                a[f][2] = __float_as_uint(tf32r(A[r * PJ_AS + k + t + 4]));
                a[f][3] = __float_as_uint(tf32r(A[(r + 8) * PJ_AS + k + t + 4]));
            }
#pragma unroll
            for (int cf = 0; cf < 8; cf++) {
                const int n = cg * 64 + cf * 8 + g;
                uint32_t b0 = __float_as_uint(tf32r(Bm[(k + t) * PJ_BS + n]));
                uint32_t b1 = __float_as_uint(tf32r(Bm[(k + t + 4) * PJ_BS + n]));
                mma8(C[0][cf], a[0], b0, b1);
                mma8(C[1][cf], a[1], b0, b1);
            }
        }
        __syncthreads();   // done reading buf before it's overwritten next+1
    }

#pragma unroll
    for (int f = 0; f < 2; f++) {
        const int r = row0 + rg * 32 + f * 16 + g;
#pragma unroll
        for (int cf = 0; cf < 8; cf++) {
            const int cb = col0 + cg * 64 + cf * 8 + 2 * t;
            float v0 = C[f][cf][0], v1 = C[f][cf][1], v2 = C[f][cf][2], v3 = C[f][cf][3];
            if (which == 0) {
                v0 = v0 * SCALE + bias[cb];     v1 = v1 * SCALE + bias[cb + 1];
                v2 = v2 * SCALE + bias[cb];     v3 = v3 * SCALE + bias[cb + 1];
            }
            *(float2*)&outp[(size_t)r * DIM + cb]       = make_float2(tf32r(v0), tf32r(v1));
            *(float2*)&outp[(size_t)(r + 8) * DIM + cb] = make_float2(tf32r(v2), tf32r(v3));
        }
    }
}

// ---------------------------------------------------------------------------
// Fused sigmoid attention via tf32 mma.sync.
// CTA: 128 Q-rows x (16 x 128-key tiles). 8 warps: rg=wid>>1 (32 rows), kg=wid&1.
// smem floats: Q[128][68] | K[128][68] | V 2x[128][72] | P[128][136]
// ---------------------------------------------------------------------------
#define AT_QS 68
#define AT_VS 72
#define AT_PS 136
#define Q_OFF 0
#define K_OFF 8704
#define V_OFF 17408
#define V_BUF 9216
#define P_OFF 35840
#define AT_SMEM ((P_OFF + 128 * AT_PS) * 4)   // 212,992 B

__global__ __launch_bounds__(256) void attn_tc(
    const float* __restrict__ x, float* __restrict__ out)
{
    extern __shared__ float sm[];
    const uint32_t sb = su32(sm);
    const int tid = threadIdx.x;
    const int wid = tid >> 5, lane = tid & 31;
    const int g = lane >> 2, t = lane & 3;
    const int rg = wid >> 1, kg = wid & 1;

    const int it = blockIdx.x, h = blockIdx.y, b = blockIdx.z;
    const size_t base = (size_t)b * N_SEQ * DIM + (size_t)h * DK;
    const float* qgm = g_Q + base + (size_t)(it * 128) * DIM;
    const float* kgm = g_K + base;
    const float* vgm = x + base;

    // 128 rows x 64 floats = 2048 x 16B chunks -> 8 per thread
    #define AT_LOAD(dstoff, stride, srcp) do {                                  \
        _Pragma("unroll")                                                       \
        for (int i = 0; i < 8; i++) {                                           \
            int c = tid + i * 256, r = c >> 4, c4 = (c & 15) << 2;              \
            CPA(sb + (uint32_t)((dstoff) + r * (stride) + c4) * 4u,             \
                (srcp) + (size_t)r * DIM + c4);                                 \
        }                                                                       \
    } while (0)

    AT_LOAD(Q_OFF, AT_QS, qgm);
    AT_LOAD(K_OFF, AT_QS, kgm);
    AT_LOAD(V_OFF, AT_VS, vgm);
    CPC();

    float O[2][4][4] = {};
    const float* Qs = sm + Q_OFF;
    const float* Ks = sm + K_OFF;
    float* Ps = sm + P_OFF;

    for (int jt = 0; jt < 16; jt++) {
        CPW(0);
        __syncthreads();    // K[jt], V[jt] ready; prev GEMM2 (P,V readers) done

        // ---- GEMM1: S(32x64 per warp) = Q K^T, dk=64 ----
        float S[2][8][4] = {};
#pragma unroll
        for (int kb = 0; kb < 8; kb++) {
            const int k = kb * 8;
            uint32_t a[2][4];
#pragma unroll
            for (int f = 0; f < 2; f++) {
                const int r = rg * 32 + f * 16 + g;
                a[f][0] = __float_as_uint(Qs[r * AT_QS + k + t]);
                a[f][1] = __float_as_uint(Qs[(r + 8) * AT_QS + k + t]);
                a[f][2] = __float_as_uint(Qs[r * AT_QS + k + t + 4]);
                a[f][3] = __float_as_uint(Qs[(r + 8) * AT_QS + k + t + 4]);
            }
#pragma unroll
            for (int cf = 0; cf < 8; cf++) {
                const int n = kg * 64 + cf * 8 + g;
                uint32_t b0 = __float_as_uint(Ks[n * AT_QS + k + t]);
                uint32_t b1 = __float_as_uint(Ks[n * AT_QS + k + t + 4]);
                mma8(S[0][cf], a[0], b0, b1);
                mma8(S[1][cf], a[1], b0, b1);
            }
        }
        __syncthreads();    // all warps done reading K -> safe to overwrite

        if (jt < 15) {
            const float* kn = kgm + (size_t)((jt + 1) * 128) * DIM;
            const float* vn = vgm + (size_t)((jt + 1) * 128) * DIM;
            AT_LOAD(K_OFF, AT_QS, kn);
            AT_LOAD(V_OFF + ((jt + 1) & 1) * V_BUF, AT_VS, vn);
            CPC();
        }

        // ---- P = tf32(sigmoid(S)) -> smem ----
#pragma unroll
        for (int f = 0; f < 2; f++) {
            const int r = rg * 32 + f * 16 + g;
            const int cb = kg * 64 + 2 * t;
#pragma unroll
            for (int cf = 0; cf < 8; cf++) {
                const int col = cb + cf * 8;
                *(float2*)&Ps[r * AT_PS + col] =
                    make_float2(tf32r(sigf(S[f][cf][0])), tf32r(sigf(S[f][cf][1])));
                *(float2*)&Ps[(r + 8) * AT_PS + col] =
                    make_float2(tf32r(sigf(S[f][cf][2])), tf32r(sigf(S[f][cf][3])));
            }
        }
        __syncthreads();    // P visible to all warps

        // ---- GEMM2: O(32x32 per warp) += P V, k = 128 keys ----
        const float* Vs = sm + V_OFF + (jt & 1) * V_BUF;
#pragma unroll
        for (int kb = 0; kb < 16; kb++) {
            const int k = kb * 8;
            uint32_t a[2][4];
#pragma unroll
            for (int f = 0; f < 2; f++) {
                const int r = rg * 32 + f * 16 + g;
                a[f][0] = __float_as_uint(Ps[r * AT_PS + k + t]);
                a[f][1] = __float_as_uint(Ps[(r + 8) * AT_PS + k + t]);
                a[f][2] = __float_as_uint(Ps[r * AT_PS + k + t + 4]);
                a[f][3] = __float_as_uint(Ps[(r + 8) * AT_PS + k + t + 4]);
            }
#pragma unroll
            for (int cf = 0; cf < 4; cf++) {
                const int d = kg * 32 + cf * 8 + g;
                uint32_t b0 = __float_as_uint(tf32r(Vs[(k + t) * AT_VS + d]));
                uint32_t b1 = __float_as_uint(tf32r(Vs[(k + t + 4) * AT_VS + d]));
                mma8(O[0][cf], a[0], b0, b1);
                mma8(O[1][cf], a[1], b0, b1);
            }
        }
    }

    // ---- epilogue ----
#pragma unroll
    for (int f = 0; f < 2; f++) {
        const int r = it * 128 + rg * 32 + f * 16 + g;
        float* og = out + ((size_t)b * N_SEQ + r) * DIM + h * DK;
#pragma unroll
        for (int cf = 0; cf < 4; cf++) {
            const int d = kg * 32 + cf * 8 + 2 * t;
            *(float2*)&og[d] = make_float2(O[f][cf][0], O[f][cf][1]);
            *(float2*)(og + (size_t)8 * DIM + d) = make_float2(O[f][cf][2], O[f][cf][3]);
        }
    }
}

extern "C" void kernel_launch(void* const* d_in, const int* in_sizes, int n_in,
                              void* d_out, int out_size)
{
    const float* x    = (const float*)d_in[0];
    const float* Wq   = (const float*)d_in[1];
    const float* Wk   = (const float*)d_in[2];
    const float* bias = (const float*)d_in[3];
    float* out = (float*)d_out;

    cudaFuncSetAttribute(proj_tc, cudaFuncAttributeMaxDynamicSharedMemorySize, PJ_SMEM);
    cudaFuncSetAttribute(attn_tc, cudaFuncAttributeMaxDynamicSharedMemorySize, AT_SMEM);

    proj_tc<<<dim3(DIM / 128, M_ROWS / 128, 2), 256, PJ_SMEM>>>(x, Wq, Wk, bias);
    attn_tc<<<dim3(N_SEQ / 128, NH, B_SZ), 256, AT_SMEM>>>(x, out);
}

// round 4
// speedup vs baseline: 3.5221x; 1.1016x over previous
#include <cuda_runtime.h>
#include <cstdint>

#define B_SZ  4
#define N_SEQ 2048
#define DIM   512
#define NH    8
#define DK    64
#define M_ROWS (B_SZ * N_SEQ)
#define SCALE 0.125f

// Scratch: projected Q (scaled+biased), K, and tf32-rounded x (V source).
__device__ float g_Q[M_ROWS * DIM];
__device__ float g_K[M_ROWS * DIM];
__device__ float g_V[M_ROWS * DIM];

// ---------------------------------------------------------------------------
// helpers (portable PTX only)
// ---------------------------------------------------------------------------
__device__ __forceinline__ float tf32r(float x) {
    float y;
    asm("cvt.rna.tf32.f32 %0, %1;" : "=f"(y) : "f"(x));
    return y;
}
__device__ __forceinline__ uint32_t su32(const void* p) {
    uint32_t a;
    asm("{ .reg .u64 t; cvta.to.shared.u64 t, %1; cvt.u32.u64 %0, t; }" : "=r"(a) : "l"(p));
    return a;
}
#define CPA(sa, gp) asm volatile("cp.async.cg.shared.global [%0], [%1], 16;" :: "r"(sa), "l"(gp))
#define CPC()  asm volatile("cp.async.commit_group;" ::: "memory")
#define CPW(n) asm volatile("cp.async.wait_group %0;" :: "n"(n) : "memory")

__device__ __forceinline__ void mma8(float* d, const uint32_t* a, uint32_t b0, uint32_t b1) {
    asm volatile(
        "mma.sync.aligned.m16n8k8.row.col.f32.tf32.tf32.f32 "
        "{%0,%1,%2,%3}, {%4,%5,%6,%7}, {%8,%9}, {%0,%1,%2,%3};"
        : "+f"(d[0]), "+f"(d[1]), "+f"(d[2]), "+f"(d[3])
        : "r"(a[0]), "r"(a[1]), "r"(a[2]), "r"(a[3]), "r"(b0), "r"(b1));
}

__device__ __forceinline__ float sigf(float x) {
    float e, r;
    asm("ex2.approx.f32 %0, %1;" : "=f"(e) : "f"(-1.4426950408889634f * x));
    asm("rcp.approx.f32 %0, %1;" : "=f"(r) : "f"(1.0f + e));
    return r;
}

// ---------------------------------------------------------------------------
// x -> tf32-rounded copy (V operand pre-rounding), 4M elems, float4 grid-stride
// ---------------------------------------------------------------------------
__global__ __launch_bounds__(256) void round_x(const float* __restrict__ x) {
    const int i = blockIdx.x * 256 + threadIdx.x;
    float4 v = reinterpret_cast<const float4*>(x)[i];
    v.x = tf32r(v.x); v.y = tf32r(v.y); v.z = tf32r(v.z); v.w = tf32r(v.w);
    reinterpret_cast<float4*>(g_V)[i] = v;
}

// ---------------------------------------------------------------------------
// Projection: g_Q = tf32(x@Wq*SCALE + bias), g_K = tf32(x@Wk)  via tf32 mma
// (unchanged from R3 — passing, ~66us; not current bottleneck)
// ---------------------------------------------------------------------------
#define PJ_AS 36
#define PJ_BS 136
#define PJ_A_SZ (128 * PJ_AS)
#define PJ_B_SZ (32 * PJ_BS)
#define PJ_SMEM ((2 * PJ_A_SZ + 2 * PJ_B_SZ) * 4)

__global__ __launch_bounds__(256) void proj_tc(
    const float* __restrict__ x, const float* __restrict__ Wq,
    const float* __restrict__ Wk, const float* __restrict__ bias)
{
    extern __shared__ float sm[];
    float* As = sm;
    float* Bs = sm + 2 * PJ_A_SZ;
    const uint32_t sb = su32(sm);

    const int which = blockIdx.z;
    const float* W = which ? Wk : Wq;
    float* outp = which ? g_K : g_Q;

    const int tid = threadIdx.x;
    const int wid = tid >> 5, lane = tid & 31;
    const int g = lane >> 2, t = lane & 3;
    const int rg = wid >> 1, cg = wid & 1;
    const int row0 = blockIdx.y * 128, col0 = blockIdx.x * 128;

    #define PJ_LOAD(kt, buf) do {                                               \
        const float* _sa = x + (size_t)row0 * DIM + (kt) * 32;                  \
        uint32_t _da = sb + (uint32_t)((buf) * PJ_A_SZ) * 4u;                   \
        _Pragma("unroll")                                                       \
        for (int i = 0; i < 4; i++) {                                           \
            int c = tid + i * 256, r = c >> 3, c4 = (c & 7) << 2;               \
            CPA(_da + (uint32_t)(r * PJ_AS + c4) * 4u, _sa + (size_t)r * DIM + c4); \
        }                                                                       \
        const float* _sbp = W + (size_t)((kt) * 32) * DIM + col0;               \
        uint32_t _db = sb + (uint32_t)(2 * PJ_A_SZ + (buf) * PJ_B_SZ) * 4u;     \
        _Pragma("unroll")                                                       \
        for (int i = 0; i < 4; i++) {                                           \
            int c = tid + i * 256, r = c >> 5, c4 = (c & 31) << 2;              \
            CPA(_db + (uint32_t)(r * PJ_BS + c4) * 4u, _sbp + (size_t)r * DIM + c4); \
        }                                                                       \
        CPC();                                                                  \
    } while (0)

    float C[2][8][4] = {};

    PJ_LOAD(0, 0);
    for (int kt = 0; kt < 16; kt++) {
        const int buf = kt & 1;
        if (kt < 15) { PJ_LOAD(kt + 1, buf ^ 1); CPW(1); } else { CPW(0); }
        __syncthreads();
        const float* A  = As + buf * PJ_A_SZ;
        const float* Bm = Bs + buf * PJ_B_SZ;
#pragma unroll
        for (int kb = 0; kb < 4; kb++) {
            const int k = kb * 8;
            uint32_t a[2][4];
#pragma unroll
            for (int f = 0; f < 2; f++) {
                const int r = rg * 32 + f * 16 + g;
                a[f][0] = __float_as_uint(tf32r(A[r * PJ_AS + k + t]));
                a[f][1] = __float_as_uint(tf32r(A[(r + 8) * PJ_AS + k + t]));
                a[f][2] = __float_as_uint(tf32r(A[r * PJ_AS + k + t + 4]));
                a[f][3] = __float_as_uint(tf32r(A[(r + 8) * PJ_AS + k + t + 4]));
            }
#pragma unroll
            for (int cf = 0; cf < 8; cf++) {
                const int n = cg * 64 + cf * 8 + g;
                uint32_t b0 = __float_as_uint(tf32r(Bm[(k + t) * PJ_BS + n]));
                uint32_t b1 = __float_as_uint(tf32r(Bm[(k + t + 4) * PJ_BS + n]));
                mma8(C[0][cf], a[0], b0, b1);
                mma8(C[1][cf], a[1], b0, b1);
            }
        }
        __syncthreads();
    }

#pragma unroll
    for (int f = 0; f < 2; f++) {
        const int r = row0 + rg * 32 + f * 16 + g;
#pragma unroll
        for (int cf = 0; cf < 8; cf++) {
            const int cb = col0 + cg * 64 + cf * 8 + 2 * t;
            float v0 = C[f][cf][0], v1 = C[f][cf][1], v2 = C[f][cf][2], v3 = C[f][cf][3];
            if (which == 0) {
                v0 = v0 * SCALE + bias[cb];     v1 = v1 * SCALE + bias[cb + 1];
                v2 = v2 * SCALE + bias[cb];     v3 = v3 * SCALE + bias[cb + 1];
            }
            *(float2*)&outp[(size_t)r * DIM + cb]       = make_float2(tf32r(v0), tf32r(v1));
            *(float2*)&outp[(size_t)(r + 8) * DIM + cb] = make_float2(tf32r(v2), tf32r(v3));
        }
    }
}

// ---------------------------------------------------------------------------
// Fused sigmoid attention, warp-autonomous strips.
// CTA = 128 Q-rows, 8 warps, warp w owns rows [w*16, w*16+16).
// Per jt (128-key tile): S(16x128)=Q K^T (Q frags in regs);
// P = tf32(sigmoid(S)) in regs; C-frag -> A-frag via quad shuffles;
// O(16x64) += P V. Only ONE __syncthreads per jt (K/V double-buffer swap).
// smem: K 2x[128][68] + V 2x[128][72] = 143,360 B.
// ---------------------------------------------------------------------------
#define KT  128
#define NT  (N_SEQ / KT)
#define KS  68
#define VS  72
#define K_BUF (128 * KS)
#define VOFF0 (2 * K_BUF)
#define V_BUF (128 * VS)
#define AT_SMEM ((2 * K_BUF + 2 * V_BUF) * 4)

__global__ __launch_bounds__(256, 1) void attn_tc(
    float* __restrict__ out)
{
    extern __shared__ float sm[];
    const uint32_t sb = su32(sm);
    const int tid = threadIdx.x;
    const int wid = tid >> 5, lane = tid & 31;
    const int g = lane >> 2, t = lane & 3;

    const int it = blockIdx.x, h = blockIdx.y, b = blockIdx.z;
    const size_t base = (size_t)b * N_SEQ * DIM + (size_t)h * DK;
    const float* qgm = g_Q + base + (size_t)(it * 128) * DIM;
    const float* kgm = g_K + base;
    const float* vgm = g_V + base;

    // Q fragments (rows wid*16+g, +8), one-time gmem load
    uint32_t qf[8][4];
    {
        const float* q0 = qgm + (size_t)(wid * 16 + g) * DIM;
        const float* q1 = q0 + (size_t)8 * DIM;
#pragma unroll
        for (int kb = 0; kb < 8; kb++) {
            qf[kb][0] = __float_as_uint(q0[8 * kb + t]);
            qf[kb][1] = __float_as_uint(q1[8 * kb + t]);
            qf[kb][2] = __float_as_uint(q0[8 * kb + t + 4]);
            qf[kb][3] = __float_as_uint(q1[8 * kb + t + 4]);
        }
    }

    #define LOAD_TILE(jt_) do {                                                 \
        const int _buf = (jt_) & 1;                                             \
        const float* _ks = kgm + (size_t)((jt_) * KT) * DIM;                    \
        const float* _vs = vgm + (size_t)((jt_) * KT) * DIM;                    \
        uint32_t _kd = sb + (uint32_t)(_buf * K_BUF) * 4u;                      \
        uint32_t _vd = sb + (uint32_t)(VOFF0 + _buf * V_BUF) * 4u;              \
        _Pragma("unroll")                                                       \
        for (int i = 0; i < 8; i++) {                                           \
            int c = tid + i * 256, r = c >> 4, c4 = (c & 15) << 2;              \
            CPA(_kd + (uint32_t)(r * KS + c4) * 4u, _ks + (size_t)r * DIM + c4);\
            CPA(_vd + (uint32_t)(r * VS + c4) * 4u, _vs + (size_t)r * DIM + c4);\
        }                                                                       \
        CPC();                                                                  \
    } while (0)

    float O[8][4] = {};

    LOAD_TILE(0);

    for (int jt = 0; jt < NT; jt++) {
        CPW(0);
        __syncthreads();                 // tile jt visible; buf (jt+1)&1 free
        if (jt + 1 < NT) LOAD_TILE(jt + 1);

        const float* Ks = sm + (jt & 1) * K_BUF;
        const float* Vs = sm + VOFF0 + (jt & 1) * V_BUF;

        // ---- GEMM1: S(16x128) = Q K^T, dk = 64 ----
        float S[16][4] = {};
#pragma unroll
        for (int kb = 0; kb < 8; kb++) {
            const int k = kb * 8;
#pragma unroll
            for (int nf = 0; nf < 16; nf++) {
                const int n = nf * 8 + g;
                uint32_t b0 = __float_as_uint(Ks[n * KS + k + t]);
                uint32_t b1 = __float_as_uint(Ks[n * KS + k + t + 4]);
                mma8(S[nf], qf[kb], b0, b1);
            }
        }

        // ---- P = tf32(sigmoid(S)) (in C-frag layout) ----
#pragma unroll
        for (int nf = 0; nf < 16; nf++)
#pragma unroll
            for (int i = 0; i < 4; i++)
                S[nf][i] = tf32r(sigf(S[nf][i]));

        // ---- GEMM2: O(16x64) += P V ; C-frag -> A-frag via quad shuffles ----
        const int src0 = (lane & ~3) | (t >> 1);
        const int src1 = src0 + 2;
        const bool odd = t & 1;
#pragma unroll
        for (int kt = 0; kt < 16; kt++) {
            float x0 = __shfl_sync(0xFFFFFFFFu, S[kt][0], src0);
            float x1 = __shfl_sync(0xFFFFFFFFu, S[kt][1], src0);
            float x2 = __shfl_sync(0xFFFFFFFFu, S[kt][2], src0);
            float x3 = __shfl_sync(0xFFFFFFFFu, S[kt][3], src0);
            float y0 = __shfl_sync(0xFFFFFFFFu, S[kt][0], src1);
            float y1 = __shfl_sync(0xFFFFFFFFu, S[kt][1], src1);
            float y2 = __shfl_sync(0xFFFFFFFFu, S[kt][2], src1);
            float y3 = __shfl_sync(0xFFFFFFFFu, S[kt][3], src1);
            uint32_t a[4];
            a[0] = __float_as_uint(odd ? x1 : x0);   // (g,    kt*8+t)
            a[1] = __float_as_uint(odd ? x3 : x2);   // (g+8,  kt*8+t)
            a[2] = __float_as_uint(odd ? y1 : y0);   // (g,    kt*8+t+4)
            a[3] = __float_as_uint(odd ? y3 : y2);   // (g+8,  kt*8+t+4)
            const int k = kt * 8;
#pragma unroll
            for (int nf = 0; nf < 8; nf++) {
                const int d = nf * 8 + g;
                uint32_t b0 = __float_as_uint(Vs[(k + t) * VS + d]);
                uint32_t b1 = __float_as_uint(Vs[(k + t + 4) * VS + d]);
                mma8(O[nf], a, b0, b1);
            }
        }
    }

    // ---- epilogue ----
    {
        const int r0 = it * 128 + wid * 16 + g;
        float* og = out + ((size_t)b * N_SEQ + r0) * DIM + h * DK;
#pragma unroll
        for (int nf = 0; nf < 8; nf++) {
            const int d = nf * 8 + 2 * t;
            *(float2*)&og[d] = make_float2(O[nf][0], O[nf][1]);
            *(float2*)(og + (size_t)8 * DIM + d) = make_float2(O[nf][2], O[nf][3]);
        }
    }
}

extern "C" void kernel_launch(void* const* d_in, const int* in_sizes, int n_in,
                              void* d_out, int out_size)
{
    const float* x    = (const float*)d_in[0];
    const float* Wq   = (const float*)d_in[1];
    const float* Wk   = (const float*)d_in[2];
    const float* bias = (const float*)d_in[3];
    float* out = (float*)d_out;

    cudaFuncSetAttribute(proj_tc, cudaFuncAttributeMaxDynamicSharedMemorySize, PJ_SMEM);
    cudaFuncSetAttribute(attn_tc, cudaFuncAttributeMaxDynamicSharedMemorySize, AT_SMEM);

    round_x<<<M_ROWS * DIM / 4 / 256, 256>>>(x);
    proj_tc<<<dim3(DIM / 128, M_ROWS / 128, 2), 256, PJ_SMEM>>>(x, Wq, Wk, bias);
    attn_tc<<<dim3(N_SEQ / 128, NH, B_SZ), 256, AT_SMEM>>>(out);
}

// round 5
// speedup vs baseline: 6.6011x; 1.8742x over previous
#include <cuda_runtime.h>
#include <cuda_fp16.h>
#include <cstdint>

#define B_SZ  4
#define N_SEQ 2048
#define DIM   512
#define NH    8
#define DK    64
#define M_ROWS (B_SZ * N_SEQ)
#define SCALE 0.125f

// Scratch: projected Q (scaled+biased), K, and V (= x) — all fp16.
__device__ __half g_Q[M_ROWS * DIM];
__device__ __half g_K[M_ROWS * DIM];
__device__ __half g_V[M_ROWS * DIM];

// ---------------------------------------------------------------------------
// helpers (portable PTX, sm_80-class only)
// ---------------------------------------------------------------------------
__device__ __forceinline__ float tf32r(float x) {
    float y;
    asm("cvt.rna.tf32.f32 %0, %1;" : "=f"(y) : "f"(x));
    return y;
}
__device__ __forceinline__ uint32_t su32(const void* p) {
    uint32_t a;
    asm("{ .reg .u64 t; cvta.to.shared.u64 t, %1; cvt.u32.u64 %0, t; }" : "=r"(a) : "l"(p));
    return a;
}
#define CPA(sa, gp) asm volatile("cp.async.cg.shared.global [%0], [%1], 16;" :: "r"(sa), "l"(gp))
#define CPC()  asm volatile("cp.async.commit_group;" ::: "memory")
#define CPW(n) asm volatile("cp.async.wait_group %0;" :: "n"(n) : "memory")

// tf32 m16n8k8 (projection kernel)
__device__ __forceinline__ void mma8(float* d, const uint32_t* a, uint32_t b0, uint32_t b1) {
    asm volatile(
        "mma.sync.aligned.m16n8k8.row.col.f32.tf32.tf32.f32 "
        "{%0,%1,%2,%3}, {%4,%5,%6,%7}, {%8,%9}, {%0,%1,%2,%3};"
        : "+f"(d[0]), "+f"(d[1]), "+f"(d[2]), "+f"(d[3])
        : "r"(a[0]), "r"(a[1]), "r"(a[2]), "r"(a[3]), "r"(b0), "r"(b1));
}
// fp16 m16n8k16, fp32 accum (attention)
__device__ __forceinline__ void mma16(float* d, const uint32_t* a, uint32_t b0, uint32_t b1) {
    asm volatile(
        "mma.sync.aligned.m16n8k16.row.col.f32.f16.f16.f32 "
        "{%0,%1,%2,%3}, {%4,%5,%6,%7}, {%8,%9}, {%0,%1,%2,%3};"
        : "+f"(d[0]), "+f"(d[1]), "+f"(d[2]), "+f"(d[3])
        : "r"(a[0]), "r"(a[1]), "r"(a[2]), "r"(a[3]), "r"(b0), "r"(b1));
}
#define LDSM4(r0, r1, r2, r3, addr)                                            \
    asm volatile("ldmatrix.sync.aligned.m8n8.x4.shared.b16 {%0,%1,%2,%3}, [%4];" \
        : "=r"(r0), "=r"(r1), "=r"(r2), "=r"(r3) : "r"(addr))
#define LDSM4T(r0, r1, r2, r3, addr)                                           \
    asm volatile("ldmatrix.sync.aligned.m8n8.x4.trans.shared.b16 {%0,%1,%2,%3}, [%4];" \
        : "=r"(r0), "=r"(r1), "=r"(r2), "=r"(r3) : "r"(addr))

__device__ __forceinline__ float sigt(float x) {
    float t;
    asm("tanh.approx.f32 %0, %1;" : "=f"(t) : "f"(0.5f * x));
    return 0.5f * t + 0.5f;
}

// ---------------------------------------------------------------------------
// x (f32) -> g_V (fp16)
// ---------------------------------------------------------------------------
__global__ __launch_bounds__(256) void round_x(const float* __restrict__ x) {
    const int i = blockIdx.x * 256 + threadIdx.x;
    float4 v = reinterpret_cast<const float4*>(x)[i];
    __half2 h0 = __floats2half2_rn(v.x, v.y);
    __half2 h1 = __floats2half2_rn(v.z, v.w);
    uint2 u;
    u.x = *reinterpret_cast<uint32_t*>(&h0);
    u.y = *reinterpret_cast<uint32_t*>(&h1);
    reinterpret_cast<uint2*>(g_V)[i] = u;
}

// ---------------------------------------------------------------------------
// Projection (tf32 mma, unchanged math): g_Q = h(x@Wq*SCALE+bias), g_K = h(x@Wk)
// ---------------------------------------------------------------------------
#define PJ_AS 36
#define PJ_BS 136
#define PJ_A_SZ (128 * PJ_AS)
#define PJ_B_SZ (32 * PJ_BS)
#define PJ_SMEM ((2 * PJ_A_SZ + 2 * PJ_B_SZ) * 4)

__global__ __launch_bounds__(256) void proj_tc(
    const float* __restrict__ x, const float* __restrict__ Wq,
    const float* __restrict__ Wk, const float* __restrict__ bias)
{
    extern __shared__ float sm[];
    float* As = sm;
    float* Bs = sm + 2 * PJ_A_SZ;
    const uint32_t sb = su32(sm);

    const int which = blockIdx.z;
    const float* W = which ? Wk : Wq;
    __half* outp = which ? g_K : g_Q;

    const int tid = threadIdx.x;
    const int wid = tid >> 5, lane = tid & 31;
    const int g = lane >> 2, t = lane & 3;
    const int rg = wid >> 1, cg = wid & 1;
    const int row0 = blockIdx.y * 128, col0 = blockIdx.x * 128;

    #define PJ_LOAD(kt, buf) do {                                               \
        const float* _sa = x + (size_t)row0 * DIM + (kt) * 32;                  \
        uint32_t _da = sb + (uint32_t)((buf) * PJ_A_SZ) * 4u;                   \
        _Pragma("unroll")                                                       \
        for (int i = 0; i < 4; i++) {                                           \
            int c = tid + i * 256, r = c >> 3, c4 = (c & 7) << 2;               \
            CPA(_da + (uint32_t)(r * PJ_AS + c4) * 4u, _sa + (size_t)r * DIM + c4); \
        }                                                                       \
        const float* _sbp = W + (size_t)((kt) * 32) * DIM + col0;               \
        uint32_t _db = sb + (uint32_t)(2 * PJ_A_SZ + (buf) * PJ_B_SZ) * 4u;     \
        _Pragma("unroll")                                                       \
        for (int i = 0; i < 4; i++) {                                           \
            int c = tid + i * 256, r = c >> 5, c4 = (c & 31) << 2;              \
            CPA(_db + (uint32_t)(r * PJ_BS + c4) * 4u, _sbp + (size_t)r * DIM + c4); \
        }                                                                       \
        CPC();                                                                  \
    } while (0)

    float C[2][8][4] = {};

    PJ_LOAD(0, 0);
    for (int kt = 0; kt < 16; kt++) {
        const int buf = kt & 1;
        if (kt < 15) { PJ_LOAD(kt + 1, buf ^ 1); CPW(1); } else { CPW(0); }
        __syncthreads();
        const float* A  = As + buf * PJ_A_SZ;
        const float* Bm = Bs + buf * PJ_B_SZ;
#pragma unroll
        for (int kb = 0; kb < 4; kb++) {
            const int k = kb * 8;
            uint32_t a[2][4];
#pragma unroll
            for (int f = 0; f < 2; f++) {
                const int r = rg * 32 + f * 16 + g;
                a[f][0] = __float_as_uint(tf32r(A[r * PJ_AS + k + t]));
                a[f][1] = __float_as_uint(tf32r(A[(r + 8) * PJ_AS + k + t]));
                a[f][2] = __float_as_uint(tf32r(A[r * PJ_AS + k + t + 4]));
                a[f][3] = __float_as_uint(tf32r(A[(r + 8) * PJ_AS + k + t + 4]));
            }
#pragma unroll
            for (int cf = 0; cf < 8; cf++) {
                const int n = cg * 64 + cf * 8 + g;
                uint32_t b0 = __float_as_uint(tf32r(Bm[(k + t) * PJ_BS + n]));
                uint32_t b1 = __float_as_uint(tf32r(Bm[(k + t + 4) * PJ_BS + n]));
                mma8(C[0][cf], a[0], b0, b1);
                mma8(C[1][cf], a[1], b0, b1);
            }
        }
        __syncthreads();
    }

#pragma unroll
    for (int f = 0; f < 2; f++) {
        const int r = row0 + rg * 32 + f * 16 + g;
#pragma unroll
        for (int cf = 0; cf < 8; cf++) {
            const int cb = col0 + cg * 64 + cf * 8 + 2 * t;
            float v0 = C[f][cf][0], v1 = C[f][cf][1], v2 = C[f][cf][2], v3 = C[f][cf][3];
            if (which == 0) {
                v0 = v0 * SCALE + bias[cb];     v1 = v1 * SCALE + bias[cb + 1];
                v2 = v2 * SCALE + bias[cb];     v3 = v3 * SCALE + bias[cb + 1];
            }
            *(__half2*)&outp[(size_t)r * DIM + cb]       = __floats2half2_rn(v0, v1);
            *(__half2*)&outp[(size_t)(r + 8) * DIM + cb] = __floats2half2_rn(v2, v3);
        }
    }
}

// ---------------------------------------------------------------------------
// Fused sigmoid attention, fp16 mma + ldmatrix, warp-autonomous 16-row strips.
// CTA = 128 Q-rows (8 warps x 16 rows), key tile = 64, 32 iterations.
// Per jt: S(16x64)=Q K^T (ldsm B-frags); P = h2(sig(S)) in regs (C->A direct);
// O(16x64) += P V (ldsm.trans B-frags). ONE syncthreads per jt.
// smem: K 2x[64][72] + V 2x[64][72] halves = 36,864 B -> 2 CTAs/SM.
// ---------------------------------------------------------------------------
#define KT  64
#define NT  (N_SEQ / KT)
#define KS  72
#define K_BUF (KT * KS)
#define VOFF0 (2 * K_BUF)
#define AT_SMEM ((4 * K_BUF) * 2)

__global__ __launch_bounds__(256, 2) void attn_tc(float* __restrict__ out)
{
    extern __shared__ __half smh[];
    const uint32_t sb = su32(smh);
    const int tid = threadIdx.x;
    const int wid = tid >> 5, lane = tid & 31;
    const int g = lane >> 2, t = lane & 3;

    const int it = blockIdx.x, h = blockIdx.y, b = blockIdx.z;
    const size_t base = (size_t)b * N_SEQ * DIM + (size_t)h * DK;
    const __half* qgm = g_Q + base + (size_t)(it * 128) * DIM;
    const __half* kgm = g_K + base;
    const __half* vgm = g_V + base;

    // ldmatrix lane -> matrix row address precompute
    const int lq = lane >> 3;            // matrix index 0..3
    const int lr = lane & 7;             // row within matrix
    // GEMM1 (K, non-trans): row = n0 + ((lq>>1)<<3) + lr, col = k0 + ((lq&1)<<3)
    const int k_row = ((lq >> 1) << 3) + lr;
    const int k_col = (lq & 1) << 3;
    // GEMM2 (V, trans): row = k0 + ((lq&1)<<3) + lr, col = n0 + ((lq>>1)<<3)
    const int v_row = ((lq & 1) << 3) + lr;
    const int v_col = (lq >> 1) << 3;

    // Q fragments: 4 k-blocks x 4 half2 regs, rows wid*16+g / +8
    uint32_t qf[4][4];
    {
        const __half* q0 = qgm + (size_t)(wid * 16 + g) * DIM;
        const __half* q1 = q0 + (size_t)8 * DIM;
#pragma unroll
        for (int kb = 0; kb < 4; kb++) {
            qf[kb][0] = *(const uint32_t*)(q0 + 16 * kb + 2 * t);
            qf[kb][1] = *(const uint32_t*)(q1 + 16 * kb + 2 * t);
            qf[kb][2] = *(const uint32_t*)(q0 + 16 * kb + 8 + 2 * t);
            qf[kb][3] = *(const uint32_t*)(q1 + 16 * kb + 8 + 2 * t);
        }
    }

    // 64 rows x 64 halves = 128B/row = 8 x 16B chunks; 512 chunks / 256 thr = 2 per tensor
    #define LOAD_TILE(jt_) do {                                                 \
        const int _buf = (jt_) & 1;                                             \
        const __half* _ks = kgm + (size_t)((jt_) * KT) * DIM;                   \
        const __half* _vs = vgm + (size_t)((jt_) * KT) * DIM;                   \
        uint32_t _kd = sb + (uint32_t)(_buf * K_BUF) * 2u;                      \
        uint32_t _vd = sb + (uint32_t)(VOFF0 + _buf * K_BUF) * 2u;              \
        _Pragma("unroll")                                                       \
        for (int i = 0; i < 2; i++) {                                           \
            int c = tid + i * 256, r = c >> 3, c8 = (c & 7) << 3;               \
            CPA(_kd + (uint32_t)(r * KS + c8) * 2u, _ks + (size_t)r * DIM + c8);\
            CPA(_vd + (uint32_t)(r * KS + c8) * 2u, _vs + (size_t)r * DIM + c8);\
        }                                                                       \
        CPC();                                                                  \
    } while (0)

    float O[8][4] = {};

    LOAD_TILE(0);

    for (int jt = 0; jt < NT; jt++) {
        CPW(0);
        __syncthreads();                 // tile jt visible; buf (jt+1)&1 free
        if (jt + 1 < NT) LOAD_TILE(jt + 1);

        const uint32_t ksb = sb + (uint32_t)((jt & 1) * K_BUF) * 2u;
        const uint32_t vsb = sb + (uint32_t)(VOFF0 + (jt & 1) * K_BUF) * 2u;

        // ---- GEMM1: S(16x64) = Q K^T, dk=64 (4 k-blocks of 16) ----
        float S[8][4] = {};
#pragma unroll
        for (int kb = 0; kb < 4; kb++) {
            const int k0 = kb * 16;
#pragma unroll
            for (int nf2 = 0; nf2 < 4; nf2++) {
                const int n0 = nf2 * 16;
                uint32_t r0, r1, r2, r3;
                LDSM4(r0, r1, r2, r3,
                      ksb + (uint32_t)((n0 + k_row) * KS + k0 + k_col) * 2u);
                mma16(S[2 * nf2],     qf[kb], r0, r1);
                mma16(S[2 * nf2 + 1], qf[kb], r2, r3);
            }
        }

        // ---- P = h2(sigmoid(S)) : C-frag -> A-frag, no shuffles ----
        uint32_t pa[4][4];
#pragma unroll
        for (int kt = 0; kt < 4; kt++) {
            __half2 h;
            h = __floats2half2_rn(sigt(S[2 * kt][0]),     sigt(S[2 * kt][1]));
            pa[kt][0] = *reinterpret_cast<uint32_t*>(&h);
            h = __floats2half2_rn(sigt(S[2 * kt][2]),     sigt(S[2 * kt][3]));
            pa[kt][1] = *reinterpret_cast<uint32_t*>(&h);
            h = __floats2half2_rn(sigt(S[2 * kt + 1][0]), sigt(S[2 * kt + 1][1]));
            pa[kt][2] = *reinterpret_cast<uint32_t*>(&h);
            h = __floats2half2_rn(sigt(S[2 * kt + 1][2]), sigt(S[2 * kt + 1][3]));
            pa[kt][3] = *reinterpret_cast<uint32_t*>(&h);
        }

        // ---- GEMM2: O(16x64) += P V (4 key-blocks of 16) ----
#pragma unroll
        for (int kt = 0; kt < 4; kt++) {
            const int k0 = kt * 16;
#pragma unroll
            for (int nf2 = 0; nf2 < 4; nf2++) {
                const int n0 = nf2 * 16;
                uint32_t r0, r1, r2, r3;
                LDSM4T(r0, r1, r2, r3,
                       vsb + (uint32_t)((k0 + v_row) * KS + n0 + v_col) * 2u);
                mma16(O[2 * nf2],     pa[kt], r0, r1);
                mma16(O[2 * nf2 + 1], pa[kt], r2, r3);
            }
        }
    }

    // ---- epilogue: O f32 -> out ----
    {
        const int r0 = it * 128 + wid * 16 + g;
        float* og = out + ((size_t)b * N_SEQ + r0) * DIM + h * DK;
#pragma unroll
        for (int nf = 0; nf < 8; nf++) {
            const int d = nf * 8 + 2 * t;
            *(float2*)&og[d] = make_float2(O[nf][0], O[nf][1]);
            *(float2*)(og + (size_t)8 * DIM + d) = make_float2(O[nf][2], O[nf][3]);
        }
    }
}

extern "C" void kernel_launch(void* const* d_in, const int* in_sizes, int n_in,
                              void* d_out, int out_size)
{
    const float* x    = (const float*)d_in[0];
    const float* Wq   = (const float*)d_in[1];
    const float* Wk   = (const float*)d_in[2];
    const float* bias = (const float*)d_in[3];
    float* out = (float*)d_out;

    cudaFuncSetAttribute(proj_tc, cudaFuncAttributeMaxDynamicSharedMemorySize, PJ_SMEM);

    round_x<<<M_ROWS * DIM / 4 / 256, 256>>>(x);
    proj_tc<<<dim3(DIM / 128, M_ROWS / 128, 2), 256, PJ_SMEM>>>(x, Wq, Wk, bias);
    attn_tc<<<dim3(N_SEQ / 128, NH, B_SZ), 256, AT_SMEM>>>(out);
}

// round 6
// speedup vs baseline: 7.8646x; 1.1914x over previous
#include <cuda_runtime.h>
#include <cuda_fp16.h>
#include <cstdint>

#define B_SZ  4
#define N_SEQ 2048
#define DIM   512
#define NH    8
#define DK    64
#define M_ROWS (B_SZ * N_SEQ)
#define SCALE 0.125f

// Scratch: projected Q (scaled+biased), K, V (= x), and fp16 weights.
__device__ __half g_Q[M_ROWS * DIM];
__device__ __half g_K[M_ROWS * DIM];
__device__ __half g_V[M_ROWS * DIM];
__device__ __half g_Wq[DIM * DIM];
__device__ __half g_Wk[DIM * DIM];

// ---------------------------------------------------------------------------
// helpers (portable PTX, sm_80-class only)
// ---------------------------------------------------------------------------
__device__ __forceinline__ uint32_t su32(const void* p) {
    uint32_t a;
    asm("{ .reg .u64 t; cvta.to.shared.u64 t, %1; cvt.u32.u64 %0, t; }" : "=r"(a) : "l"(p));
    return a;
}
#define CPA(sa, gp) asm volatile("cp.async.cg.shared.global [%0], [%1], 16;" :: "r"(sa), "l"(gp))
#define CPC()  asm volatile("cp.async.commit_group;" ::: "memory")
#define CPW(n) asm volatile("cp.async.wait_group %0;" :: "n"(n) : "memory")

// fp16 m16n8k16, fp32 accum
__device__ __forceinline__ void mma16(float* d, const uint32_t* a, uint32_t b0, uint32_t b1) {
    asm volatile(
        "mma.sync.aligned.m16n8k16.row.col.f32.f16.f16.f32 "
        "{%0,%1,%2,%3}, {%4,%5,%6,%7}, {%8,%9}, {%0,%1,%2,%3};"
        : "+f"(d[0]), "+f"(d[1]), "+f"(d[2]), "+f"(d[3])
        : "r"(a[0]), "r"(a[1]), "r"(a[2]), "r"(a[3]), "r"(b0), "r"(b1));
}
#define LDSM4(r0, r1, r2, r3, addr)                                            \
    asm volatile("ldmatrix.sync.aligned.m8n8.x4.shared.b16 {%0,%1,%2,%3}, [%4];" \
        : "=r"(r0), "=r"(r1), "=r"(r2), "=r"(r3) : "r"(addr))
#define LDSM4T(r0, r1, r2, r3, addr)                                           \
    asm volatile("ldmatrix.sync.aligned.m8n8.x4.trans.shared.b16 {%0,%1,%2,%3}, [%4];" \
        : "=r"(r0), "=r"(r1), "=r"(r2), "=r"(r3) : "r"(addr))

__device__ __forceinline__ float sigt(float x) {
    float t;
    asm("tanh.approx.f32 %0, %1;" : "=f"(t) : "f"(0.5f * x));
    return 0.5f * t + 0.5f;
}

// ---------------------------------------------------------------------------
// x (f32) -> g_V (fp16)
// ---------------------------------------------------------------------------
__global__ __launch_bounds__(256) void round_x(const float* __restrict__ x) {
    const int i = blockIdx.x * 256 + threadIdx.x;
    float4 v = reinterpret_cast<const float4*>(x)[i];
    __half2 h0 = __floats2half2_rn(v.x, v.y);
    __half2 h1 = __floats2half2_rn(v.z, v.w);
    uint2 u;
    u.x = *reinterpret_cast<uint32_t*>(&h0);
    u.y = *reinterpret_cast<uint32_t*>(&h1);
    reinterpret_cast<uint2*>(g_V)[i] = u;
}

// Wq, Wk (f32) -> g_Wq, g_Wk (fp16). 2 x 65536 float4 chunks.
__global__ __launch_bounds__(256) void wconv(const float* __restrict__ Wq,
                                             const float* __restrict__ Wk) {
    const int i = blockIdx.x * 256 + threadIdx.x;
    const int half_n = DIM * DIM / 4;                 // 65536
    const float* src = (i < half_n) ? Wq : Wk;
    __half* dst = (i < half_n) ? g_Wq : g_Wk;
    const int j = (i < half_n) ? i : i - half_n;
    float4 v = reinterpret_cast<const float4*>(src)[j];
    __half2 h0 = __floats2half2_rn(v.x, v.y);
    __half2 h1 = __floats2half2_rn(v.z, v.w);
    uint2 u;
    u.x = *reinterpret_cast<uint32_t*>(&h0);
    u.y = *reinterpret_cast<uint32_t*>(&h1);
    reinterpret_cast<uint2*>(dst)[j] = u;
}

// ---------------------------------------------------------------------------
// Projection, fp16 mma + ldmatrix: g_Q = h(xh@Wqh*SCALE+bias), g_K = h(xh@Wkh)
// CTA tile 128(M) x 128(N), k-tile 64, 256 threads (8 warps 4x2), 2-stage.
// smem halves: A 2x[128][72] | B 2x[64][136]  = 71,680 B
// ---------------------------------------------------------------------------
#define P2_AS 72
#define P2_BS 136
#define P2_A_SZ (128 * P2_AS)
#define P2_B_SZ (64 * P2_BS)
#define P2_SMEM ((2 * P2_A_SZ + 2 * P2_B_SZ) * 2)

__global__ __launch_bounds__(256) void proj_tc(const float* __restrict__ bias)
{
    extern __shared__ __half smh[];
    const uint32_t sb = su32(smh);
    const uint32_t sA = sb;
    const uint32_t sB = sb + (uint32_t)(2 * P2_A_SZ) * 2u;

    const int which = blockIdx.z;
    const __half* W = which ? g_Wk : g_Wq;
    __half* outp = which ? g_K : g_Q;

    const int tid = threadIdx.x;
    const int wid = tid >> 5, lane = tid & 31;
    const int g = lane >> 2, t = lane & 3;
    const int rg = wid >> 1, cg = wid & 1;
    const int row0 = blockIdx.y * 128, col0 = blockIdx.x * 128;

    // ldmatrix addressing (same convention as attention kernel)
    const int lq = lane >> 3, lr = lane & 7;
    const int a_row = ((lq >> 1) << 3) + lr;     // A non-trans
    const int a_col = (lq & 1) << 3;
    const int b_row = ((lq & 1) << 3) + lr;      // B trans ([k][n] smem)
    const int b_col = (lq >> 1) << 3;

    #define P2_LOAD(kt, buf) do {                                               \
        const __half* _sa = g_V + (size_t)row0 * DIM + (kt) * 64;               \
        uint32_t _da = sA + (uint32_t)((buf) * P2_A_SZ) * 2u;                   \
        _Pragma("unroll")                                                       \
        for (int i = 0; i < 4; i++) {                                           \
            int c = tid + i * 256, r = c >> 3, c8 = (c & 7) << 3;               \
            CPA(_da + (uint32_t)(r * P2_AS + c8) * 2u, _sa + (size_t)r * DIM + c8); \
        }                                                                       \
        const __half* _sb = W + (size_t)((kt) * 64) * DIM + col0;               \
        uint32_t _db = sB + (uint32_t)((buf) * P2_B_SZ) * 2u;                   \
        _Pragma("unroll")                                                       \
        for (int i = 0; i < 4; i++) {                                           \
            int c = tid + i * 256, r = c >> 4, c8 = (c & 15) << 3;              \
            CPA(_db + (uint32_t)(r * P2_BS + c8) * 2u, _sb + (size_t)r * DIM + c8); \
        }                                                                       \
        CPC();                                                                  \
    } while (0)

    float C[2][8][4] = {};

    P2_LOAD(0, 0);
    for (int kt = 0; kt < 8; kt++) {
        const int buf = kt & 1;
        if (kt < 7) { P2_LOAD(kt + 1, buf ^ 1); CPW(1); } else { CPW(0); }
        __syncthreads();
        const uint32_t Ab = sA + (uint32_t)(buf * P2_A_SZ) * 2u;
        const uint32_t Bb = sB + (uint32_t)(buf * P2_B_SZ) * 2u;
#pragma unroll
        for (int kb = 0; kb < 4; kb++) {
            const int k0 = kb * 16;
            uint32_t af[2][4];
#pragma unroll
            for (int f = 0; f < 2; f++) {
                uint32_t r0, r1, r2, r3;
                LDSM4(r0, r1, r2, r3,
                      Ab + (uint32_t)((rg * 32 + f * 16 + a_row) * P2_AS + k0 + a_col) * 2u);
                af[f][0] = r0; af[f][1] = r2; af[f][2] = r1; af[f][3] = r3;
            }
#pragma unroll
            for (int nf2 = 0; nf2 < 4; nf2++) {
                uint32_t r0, r1, r2, r3;
                LDSM4T(r0, r1, r2, r3,
                       Bb + (uint32_t)((k0 + b_row) * P2_BS + cg * 64 + nf2 * 16 + b_col) * 2u);
                mma16(C[0][2 * nf2],     af[0], r0, r1);
                mma16(C[0][2 * nf2 + 1], af[0], r2, r3);
                mma16(C[1][2 * nf2],     af[1], r0, r1);
                mma16(C[1][2 * nf2 + 1], af[1], r2, r3);
            }
        }
        __syncthreads();
    }

#pragma unroll
    for (int f = 0; f < 2; f++) {
        const int r = row0 + rg * 32 + f * 16 + g;
#pragma unroll
        for (int cf = 0; cf < 8; cf++) {
            const int cb = col0 + cg * 64 + cf * 8 + 2 * t;
            float v0 = C[f][cf][0], v1 = C[f][cf][1], v2 = C[f][cf][2], v3 = C[f][cf][3];
            if (which == 0) {
                v0 = v0 * SCALE + bias[cb];     v1 = v1 * SCALE + bias[cb + 1];
                v2 = v2 * SCALE + bias[cb];     v3 = v3 * SCALE + bias[cb + 1];
            }
            *(__half2*)&outp[(size_t)r * DIM + cb]       = __floats2half2_rn(v0, v1);
            *(__half2*)&outp[(size_t)(r + 8) * DIM + cb] = __floats2half2_rn(v2, v3);
        }
    }
}

// ---------------------------------------------------------------------------
// Fused sigmoid attention (unchanged from R5 — fp16 mma + ldmatrix,
// warp-autonomous 16-row strips, 1 sync/jt, 2 CTAs/SM).
// ---------------------------------------------------------------------------
#define KT  64
#define NT  (N_SEQ / KT)
#define KS  72
#define K_BUF (KT * KS)
#define VOFF0 (2 * K_BUF)
#define AT_SMEM ((4 * K_BUF) * 2)

__global__ __launch_bounds__(256, 2) void attn_tc(float* __restrict__ out)
{
    extern __shared__ __half smh[];
    const uint32_t sb = su32(smh);
    const int tid = threadIdx.x;
    const int wid = tid >> 5, lane = tid & 31;
    const int g = lane >> 2, t = lane & 3;

    const int it = blockIdx.x, h = blockIdx.y, b = blockIdx.z;
    const size_t base = (size_t)b * N_SEQ * DIM + (size_t)h * DK;
    const __half* qgm = g_Q + base + (size_t)(it * 128) * DIM;
    const __half* kgm = g_K + base;
    const __half* vgm = g_V + base;

    const int lq = lane >> 3, lr = lane & 7;
    const int k_row = ((lq >> 1) << 3) + lr;
    const int k_col = (lq & 1) << 3;
    const int v_row = ((lq & 1) << 3) + lr;
    const int v_col = (lq >> 1) << 3;

    uint32_t qf[4][4];
    {
        const __half* q0 = qgm + (size_t)(wid * 16 + g) * DIM;
        const __half* q1 = q0 + (size_t)8 * DIM;
#pragma unroll
        for (int kb = 0; kb < 4; kb++) {
            qf[kb][0] = *(const uint32_t*)(q0 + 16 * kb + 2 * t);
            qf[kb][1] = *(const uint32_t*)(q1 + 16 * kb + 2 * t);
            qf[kb][2] = *(const uint32_t*)(q0 + 16 * kb + 8 + 2 * t);
            qf[kb][3] = *(const uint32_t*)(q1 + 16 * kb + 8 + 2 * t);
        }
    }

    #define LOAD_TILE(jt_) do {                                                 \
        const int _buf = (jt_) & 1;                                             \
        const __half* _ks = kgm + (size_t)((jt_) * KT) * DIM;                   \
        const __half* _vs = vgm + (size_t)((jt_) * KT) * DIM;                   \
        uint32_t _kd = sb + (uint32_t)(_buf * K_BUF) * 2u;                      \
        uint32_t _vd = sb + (uint32_t)(VOFF0 + _buf * K_BUF) * 2u;              \
        _Pragma("unroll")                                                       \
        for (int i = 0; i < 2; i++) {                                           \
            int c = tid + i * 256, r = c >> 3, c8 = (c & 7) << 3;               \
            CPA(_kd + (uint32_t)(r * KS + c8) * 2u, _ks + (size_t)r * DIM + c8);\
            CPA(_vd + (uint32_t)(r * KS + c8) * 2u, _vs + (size_t)r * DIM + c8);\
        }                                                                       \
        CPC();                                                                  \
    } while (0)

    float O[8][4] = {};

    LOAD_TILE(0);

    for (int jt = 0; jt < NT; jt++) {
        CPW(0);
        __syncthreads();
        if (jt + 1 < NT) LOAD_TILE(jt + 1);

        const uint32_t ksb = sb + (uint32_t)((jt & 1) * K_BUF) * 2u;
        const uint32_t vsb = sb + (uint32_t)(VOFF0 + (jt & 1) * K_BUF) * 2u;

        float S[8][4] = {};
#pragma unroll
        for (int kb = 0; kb < 4; kb++) {
            const int k0 = kb * 16;
#pragma unroll
            for (int nf2 = 0; nf2 < 4; nf2++) {
                const int n0 = nf2 * 16;
                uint32_t r0, r1, r2, r3;
                LDSM4(r0, r1, r2, r3,
                      ksb + (uint32_t)((n0 + k_row) * KS + k0 + k_col) * 2u);
                mma16(S[2 * nf2],     qf[kb], r0, r1);
                mma16(S[2 * nf2 + 1], qf[kb], r2, r3);
            }
        }

        uint32_t pa[4][4];
#pragma unroll
        for (int kt = 0; kt < 4; kt++) {
            __half2 h;
            h = __floats2half2_rn(sigt(S[2 * kt][0]),     sigt(S[2 * kt][1]));
            pa[kt][0] = *reinterpret_cast<uint32_t*>(&h);
            h = __floats2half2_rn(sigt(S[2 * kt][2]),     sigt(S[2 * kt][3]));
            pa[kt][1] = *reinterpret_cast<uint32_t*>(&h);
            h = __floats2half2_rn(sigt(S[2 * kt + 1][0]), sigt(S[2 * kt + 1][1]));
            pa[kt][2] = *reinterpret_cast<uint32_t*>(&h);
            h = __floats2half2_rn(sigt(S[2 * kt + 1][2]), sigt(S[2 * kt + 1][3]));
            pa[kt][3] = *reinterpret_cast<uint32_t*>(&h);
        }

#pragma unroll
        for (int kt = 0; kt < 4; kt++) {
            const int k0 = kt * 16;
#pragma unroll
            for (int nf2 = 0; nf2 < 4; nf2++) {
                const int n0 = nf2 * 16;
                uint32_t r0, r1, r2, r3;
                LDSM4T(r0, r1, r2, r3,
                       vsb + (uint32_t)((k0 + v_row) * KS + n0 + v_col) * 2u);
                mma16(O[2 * nf2],     pa[kt], r0, r1);
                mma16(O[2 * nf2 + 1], pa[kt], r2, r3);
            }
        }
    }

    {
        const int r0 = it * 128 + wid * 16 + g;
        float* og = out + ((size_t)b * N_SEQ + r0) * DIM + h * DK;
#pragma unroll
        for (int nf = 0; nf < 8; nf++) {
            const int d = nf * 8 + 2 * t;
            *(float2*)&og[d] = make_float2(O[nf][0], O[nf][1]);
            *(float2*)(og + (size_t)8 * DIM + d) = make_float2(O[nf][2], O[nf][3]);
        }
    }
}

extern "C" void kernel_launch(void* const* d_in, const int* in_sizes, int n_in,
                              void* d_out, int out_size)
{
    const float* x    = (const float*)d_in[0];
    const float* Wq   = (const float*)d_in[1];
    const float* Wk   = (const float*)d_in[2];
    const float* bias = (const float*)d_in[3];
    float* out = (float*)d_out;

    cudaFuncSetAttribute(proj_tc, cudaFuncAttributeMaxDynamicSharedMemorySize, P2_SMEM);

    round_x<<<M_ROWS * DIM / 4 / 256, 256>>>(x);
    wconv<<<2 * DIM * DIM / 4 / 256, 256>>>(Wq, Wk);
    proj_tc<<<dim3(DIM / 128, M_ROWS / 128, 2), 256, P2_SMEM>>>(bias);
    attn_tc<<<dim3(N_SEQ / 128, NH, B_SZ), 256, AT_SMEM>>>(out);
}

// round 8
// speedup vs baseline: 8.4262x; 1.0714x over previous
#include <cuda_runtime.h>
#include <cuda_fp16.h>
#include <cstdint>

#define B_SZ  4
#define N_SEQ 2048
#define DIM   512
#define NH    8
#define DK    64
#define M_ROWS (B_SZ * N_SEQ)
#define SCALE 0.125f

// Scratch: projected Q (scaled+biased), K, V (= x), and fp16 weights.
__device__ __half g_Q[M_ROWS * DIM];
__device__ __half g_K[M_ROWS * DIM];
__device__ __half g_V[M_ROWS * DIM];
__device__ __half g_Wq[DIM * DIM];
__device__ __half g_Wk[DIM * DIM];

// ---------------------------------------------------------------------------
// helpers (portable PTX, sm_80-class only)
// ---------------------------------------------------------------------------
__device__ __forceinline__ uint32_t su32(const void* p) {
    uint32_t a;
    asm("{ .reg .u64 t; cvta.to.shared.u64 t, %1; cvt.u32.u64 %0, t; }" : "=r"(a) : "l"(p));
    return a;
}
#define CPA(sa, gp) asm volatile("cp.async.cg.shared.global [%0], [%1], 16;" :: "r"(sa), "l"(gp))
#define CPC()  asm volatile("cp.async.commit_group;" ::: "memory")
#define CPW(n) asm volatile("cp.async.wait_group %0;" :: "n"(n) : "memory")

__device__ __forceinline__ void mma16(float* d, const uint32_t* a, uint32_t b0, uint32_t b1) {
    asm volatile(
        "mma.sync.aligned.m16n8k16.row.col.f32.f16.f16.f32 "
        "{%0,%1,%2,%3}, {%4,%5,%6,%7}, {%8,%9}, {%0,%1,%2,%3};"
        : "+f"(d[0]), "+f"(d[1]), "+f"(d[2]), "+f"(d[3])
        : "r"(a[0]), "r"(a[1]), "r"(a[2]), "r"(a[3]), "r"(b0), "r"(b1));
}
#define LDSM4(r0, r1, r2, r3, addr)                                            \
    asm volatile("ldmatrix.sync.aligned.m8n8.x4.shared.b16 {%0,%1,%2,%3}, [%4];" \
        : "=r"(r0), "=r"(r1), "=r"(r2), "=r"(r3) : "r"(addr))
#define LDSM4T(r0, r1, r2, r3, addr)                                           \
    asm volatile("ldmatrix.sync.aligned.m8n8.x4.trans.shared.b16 {%0,%1,%2,%3}, [%4];" \
        : "=r"(r0), "=r"(r1), "=r"(r2), "=r"(r3) : "r"(addr))

// sigmoid on a packed half2 pair: sig(x) = 0.5*tanh(0.5*x) + 0.5
__device__ __forceinline__ uint32_t sig2(float lo, float hi) {
    __half2 v = __floats2half2_rn(0.5f * lo, 0.5f * hi);
    uint32_t u = *reinterpret_cast<uint32_t*>(&v);
    uint32_t t;
    asm("tanh.approx.f16x2 %0, %1;" : "=r"(t) : "r"(u));
    __half2 th = *reinterpret_cast<__half2*>(&t);
    __half2 hf = __floats2half2_rn(0.5f, 0.5f);
    __half2 r = __hfma2(th, hf, hf);
    return *reinterpret_cast<uint32_t*>(&r);
}

// ---------------------------------------------------------------------------
// prep: x (f32) -> g_V (fp16) ; Wq,Wk (f32) -> g_Wq,g_Wk (fp16)
// ---------------------------------------------------------------------------
#define NX  (M_ROWS * DIM / 4)        // 1,048,576 float4 chunks of x
#define NW  (DIM * DIM / 4)           // 65,536 per weight
__global__ __launch_bounds__(256) void prep(const float* __restrict__ x,
                                            const float* __restrict__ Wq,
                                            const float* __restrict__ Wk) {
    const int i = blockIdx.x * 256 + threadIdx.x;
    const float* src;
    __half* dst;
    int j;
    if (i < NX)             { src = x;  dst = g_V;  j = i; }
    else if (i < NX + NW)   { src = Wq; dst = g_Wq; j = i - NX; }
    else                    { src = Wk; dst = g_Wk; j = i - NX - NW; }
    float4 v = reinterpret_cast<const float4*>(src)[j];
    __half2 h0 = __floats2half2_rn(v.x, v.y);
    __half2 h1 = __floats2half2_rn(v.z, v.w);
    uint2 u;
    u.x = *reinterpret_cast<uint32_t*>(&h0);
    u.y = *reinterpret_cast<uint32_t*>(&h1);
    reinterpret_cast<uint2*>(dst)[j] = u;
}

// ---------------------------------------------------------------------------
// Projection, fp16 mma + ldmatrix (unchanged from R6)
// ---------------------------------------------------------------------------
#define P2_AS 72
#define P2_BS 136
#define P2_A_SZ (128 * P2_AS)
#define P2_B_SZ (64 * P2_BS)
#define P2_SMEM ((2 * P2_A_SZ + 2 * P2_B_SZ) * 2)

__global__ __launch_bounds__(256) void proj_tc(const float* __restrict__ bias)
{
    extern __shared__ __half smh[];
    const uint32_t sb = su32(smh);
    const uint32_t sA = sb;
    const uint32_t sB = sb + (uint32_t)(2 * P2_A_SZ) * 2u;

    const int which = blockIdx.z;
    const __half* W = which ? g_Wk : g_Wq;
    __half* outp = which ? g_K : g_Q;

    const int tid = threadIdx.x;
    const int wid = tid >> 5, lane = tid & 31;
    const int g = lane >> 2, t = lane & 3;
    const int rg = wid >> 1, cg = wid & 1;
    const int row0 = blockIdx.y * 128, col0 = blockIdx.x * 128;

    const int lq = lane >> 3, lr = lane & 7;
    const int a_row = ((lq >> 1) << 3) + lr;
    const int a_col = (lq & 1) << 3;
    const int b_row = ((lq & 1) << 3) + lr;
    const int b_col = (lq >> 1) << 3;

    #define P2_LOAD(kt, buf) do {                                               \
        const __half* _sa = g_V + (size_t)row0 * DIM + (kt) * 64;               \
        uint32_t _da = sA + (uint32_t)((buf) * P2_A_SZ) * 2u;                   \
        _Pragma("unroll")                                                       \
        for (int i = 0; i < 4; i++) {                                           \
            int c = tid + i * 256, r = c >> 3, c8 = (c & 7) << 3;               \
            CPA(_da + (uint32_t)(r * P2_AS + c8) * 2u, _sa + (size_t)r * DIM + c8); \
        }                                                                       \
        const __half* _sb = W + (size_t)((kt) * 64) * DIM + col0;               \
        uint32_t _db = sB + (uint32_t)((buf) * P2_B_SZ) * 2u;                   \
        _Pragma("unroll")                                                       \
        for (int i = 0; i < 4; i++) {                                           \
            int c = tid + i * 256, r = c >> 4, c8 = (c & 15) << 3;              \
            CPA(_db + (uint32_t)(r * P2_BS + c8) * 2u, _sb + (size_t)r * DIM + c8); \
        }                                                                       \
        CPC();                                                                  \
    } while (0)

    float C[2][8][4] = {};

    P2_LOAD(0, 0);
    for (int kt = 0; kt < 8; kt++) {
        const int buf = kt & 1;
        if (kt < 7) { P2_LOAD(kt + 1, buf ^ 1); CPW(1); } else { CPW(0); }
        __syncthreads();
        const uint32_t Ab = sA + (uint32_t)(buf * P2_A_SZ) * 2u;
        const uint32_t Bb = sB + (uint32_t)(buf * P2_B_SZ) * 2u;
#pragma unroll
        for (int kb = 0; kb < 4; kb++) {
            const int k0 = kb * 16;
            uint32_t af[2][4];
#pragma unroll
            for (int f = 0; f < 2; f++) {
                uint32_t r0, r1, r2, r3;
                LDSM4(r0, r1, r2, r3,
                      Ab + (uint32_t)((rg * 32 + f * 16 + a_row) * P2_AS + k0 + a_col) * 2u);
                af[f][0] = r0; af[f][1] = r2; af[f][2] = r1; af[f][3] = r3;
            }
#pragma unroll
            for (int nf2 = 0; nf2 < 4; nf2++) {
                uint32_t r0, r1, r2, r3;
                LDSM4T(r0, r1, r2, r3,
                       Bb + (uint32_t)((k0 + b_row) * P2_BS + cg * 64 + nf2 * 16 + b_col) * 2u);
                mma16(C[0][2 * nf2],     af[0], r0, r1);
                mma16(C[0][2 * nf2 + 1], af[0], r2, r3);
                mma16(C[1][2 * nf2],     af[1], r0, r1);
                mma16(C[1][2 * nf2 + 1], af[1], r2, r3);
            }
        }
        __syncthreads();
    }

#pragma unroll
    for (int f = 0; f < 2; f++) {
        const int r = row0 + rg * 32 + f * 16 + g;
#pragma unroll
        for (int cf = 0; cf < 8; cf++) {
            const int cb = col0 + cg * 64 + cf * 8 + 2 * t;
            float v0 = C[f][cf][0], v1 = C[f][cf][1], v2 = C[f][cf][2], v3 = C[f][cf][3];
            if (which == 0) {
                v0 = v0 * SCALE + bias[cb];     v1 = v1 * SCALE + bias[cb + 1];
                v2 = v2 * SCALE + bias[cb];     v3 = v3 * SCALE + bias[cb + 1];
            }
            *(__half2*)&outp[(size_t)r * DIM + cb]       = __floats2half2_rn(v0, v1);
            *(__half2*)&outp[(size_t)(r + 8) * DIM + cb] = __floats2half2_rn(v2, v3);
        }
    }
}

// ---------------------------------------------------------------------------
// Fused sigmoid attention: 4 warps x 32 Q-rows (2 m16 strips per warp).
// Each LDSM4 of K/V feeds 2 strips -> 128 mma : 32 ldsm per warp per jt.
// Sigmoid in f16x2 (tanh.approx.f16x2). 1 syncthreads per jt. 2 CTAs/SM.
// smem: K 2x[64][72] + V 2x[64][72] halves = 36,864 B.
// ---------------------------------------------------------------------------
#define KT  64
#define NT  (N_SEQ / KT)
#define KS  72
#define K_BUF (KT * KS)
#define VOFF0 (2 * K_BUF)
#define AT_SMEM ((4 * K_BUF) * 2)

__global__ __launch_bounds__(128, 2) void attn_tc(float* __restrict__ out)
{
    extern __shared__ __half smh[];
    const uint32_t sb = su32(smh);
    const int tid = threadIdx.x;
    const int wid = tid >> 5, lane = tid & 31;
    const int g = lane >> 2, t = lane & 3;

    const int it = blockIdx.x, h = blockIdx.y, b = blockIdx.z;
    const size_t base = (size_t)b * N_SEQ * DIM + (size_t)h * DK;
    const __half* qgm = g_Q + base + (size_t)(it * 128) * DIM;
    const __half* kgm = g_K + base;
    const __half* vgm = g_V + base;

    const int lq = lane >> 3, lr = lane & 7;
    const int k_row = ((lq >> 1) << 3) + lr;
    const int k_col = (lq & 1) << 3;
    const int v_row = ((lq & 1) << 3) + lr;
    const int v_col = (lq >> 1) << 3;

    // Q fragments for 2 strips (rows wid*32 + s*16 + g / +8)
    uint32_t qf[2][4][4];
#pragma unroll
    for (int s = 0; s < 2; s++) {
        const __half* q0 = qgm + (size_t)(wid * 32 + s * 16 + g) * DIM;
        const __half* q1 = q0 + (size_t)8 * DIM;
#pragma unroll
        for (int kb = 0; kb < 4; kb++) {
            qf[s][kb][0] = *(const uint32_t*)(q0 + 16 * kb + 2 * t);
            qf[s][kb][1] = *(const uint32_t*)(q1 + 16 * kb + 2 * t);
            qf[s][kb][2] = *(const uint32_t*)(q0 + 16 * kb + 8 + 2 * t);
            qf[s][kb][3] = *(const uint32_t*)(q1 + 16 * kb + 8 + 2 * t);
        }
    }

    // 64 rows x 8 16B-chunks x 2 tensors = 1024 chunks / 128 threads = 8 per thread
    #define LOAD_TILE(jt_) do {                                                 \
        const int _buf = (jt_) & 1;                                             \
        const __half* _ks = kgm + (size_t)((jt_) * KT) * DIM;                   \
        const __half* _vs = vgm + (size_t)((jt_) * KT) * DIM;                   \
        uint32_t _kd = sb + (uint32_t)(_buf * K_BUF) * 2u;                      \
        uint32_t _vd = sb + (uint32_t)(VOFF0 + _buf * K_BUF) * 2u;              \
        _Pragma("unroll")                                                       \
        for (int i = 0; i < 4; i++) {                                           \
            int c = tid + i * 128, r = c >> 3, c8 = (c & 7) << 3;               \
            CPA(_kd + (uint32_t)(r * KS + c8) * 2u, _ks + (size_t)r * DIM + c8);\
            CPA(_vd + (uint32_t)(r * KS + c8) * 2u, _vs + (size_t)r * DIM + c8);\
        }                                                                       \
        CPC();                                                                  \
    } while (0)

    float O[2][8][4] = {};

    LOAD_TILE(0);

    for (int jt = 0; jt < NT; jt++) {
        CPW(0);
        __syncthreads();
        if (jt + 1 < NT) LOAD_TILE(jt + 1);

        const uint32_t ksb = sb + (uint32_t)((jt & 1) * K_BUF) * 2u;
        const uint32_t vsb = sb + (uint32_t)(VOFF0 + (jt & 1) * K_BUF) * 2u;

        // ---- GEMM1: S(32x64) = Q K^T — each LDSM feeds both strips ----
        float S[2][8][4] = {};
#pragma unroll
        for (int kb = 0; kb < 4; kb++) {
            const int k0 = kb * 16;
#pragma unroll
            for (int nf2 = 0; nf2 < 4; nf2++) {
                const int n0 = nf2 * 16;
                uint32_t r0, r1, r2, r3;
                LDSM4(r0, r1, r2, r3,
                      ksb + (uint32_t)((n0 + k_row) * KS + k0 + k_col) * 2u);
#pragma unroll
                for (int s = 0; s < 2; s++) {
                    mma16(S[s][2 * nf2],     qf[s][kb], r0, r1);
                    mma16(S[s][2 * nf2 + 1], qf[s][kb], r2, r3);
                }
            }
        }

        // ---- P = f16x2 sigmoid(S) : C-frag -> A-frag ----
        uint32_t pa[2][4][4];
#pragma unroll
        for (int s = 0; s < 2; s++)
#pragma unroll
            for (int kt = 0; kt < 4; kt++) {
                pa[s][kt][0] = sig2(S[s][2 * kt][0],     S[s][2 * kt][1]);
                pa[s][kt][1] = sig2(S[s][2 * kt][2],     S[s][2 * kt][3]);
                pa[s][kt][2] = sig2(S[s][2 * kt + 1][0], S[s][2 * kt + 1][1]);
                pa[s][kt][3] = sig2(S[s][2 * kt + 1][2], S[s][2 * kt + 1][3]);
            }

        // ---- GEMM2: O(32x64) += P V — each LDSM feeds both strips ----
#pragma unroll
        for (int kt = 0; kt < 4; kt++) {
            const int k0 = kt * 16;
#pragma unroll
            for (int nf2 = 0; nf2 < 4; nf2++) {
                const int n0 = nf2 * 16;
                uint32_t r0, r1, r2, r3;
                LDSM4T(r0, r1, r2, r3,
                       vsb + (uint32_t)((k0 + v_row) * KS + n0 + v_col) * 2u);
#pragma unroll
                for (int s = 0; s < 2; s++) {
                    mma16(O[s][2 * nf2],     pa[s][kt], r0, r1);
                    mma16(O[s][2 * nf2 + 1], pa[s][kt], r2, r3);
                }
            }
        }
    }

    // ---- epilogue ----
#pragma unroll
    for (int s = 0; s < 2; s++) {
        const int r0 = it * 128 + wid * 32 + s * 16 + g;
        float* og = out + ((size_t)b * N_SEQ + r0) * DIM + h * DK;
#pragma unroll
        for (int nf = 0; nf < 8; nf++) {
            const int d = nf * 8 + 2 * t;
            *(float2*)&og[d] = make_float2(O[s][nf][0], O[s][nf][1]);
            *(float2*)(og + (size_t)8 * DIM + d) = make_float2(O[s][nf][2], O[s][nf][3]);
        }
    }
}

extern "C" void kernel_launch(void* const* d_in, const int* in_sizes, int n_in,
                              void* d_out, int out_size)
{
    const float* x    = (const float*)d_in[0];
    const float* Wq   = (const float*)d_in[1];
    const float* Wk   = (const float*)d_in[2];
    const float* bias = (const float*)d_in[3];
    float* out = (float*)d_out;

    cudaFuncSetAttribute(proj_tc, cudaFuncAttributeMaxDynamicSharedMemorySize, P2_SMEM);

    prep<<<(NX + 2 * NW + 255) / 256, 256>>>(x, Wq, Wk);
    proj_tc<<<dim3(DIM / 128, M_ROWS / 128, 2), 256, P2_SMEM>>>(bias);
    attn_tc<<<dim3(N_SEQ / 128, NH, B_SZ), 128, AT_SMEM>>>(out);
}

// round 9
// speedup vs baseline: 8.4393x; 1.0016x over previous
#include <cuda_runtime.h>
#include <cuda_fp16.h>
#include <cstdint>

#define B_SZ  4
#define N_SEQ 2048
#define DIM   512
#define NH    8
#define DK    64
#define M_ROWS (B_SZ * N_SEQ)
#define SCALE 0.125f

// Scratch: projected Q (pre-scaled for tanh-sigmoid), K, V (= x), fp16 weights.
__device__ __half g_Q[M_ROWS * DIM];
__device__ __half g_K[M_ROWS * DIM];
__device__ __half g_V[M_ROWS * DIM];
__device__ __half g_Wq[DIM * DIM];
__device__ __half g_Wk[DIM * DIM];

// ---------------------------------------------------------------------------
// helpers (portable PTX, sm_80-class only)
// ---------------------------------------------------------------------------
__device__ __forceinline__ uint32_t su32(const void* p) {
    uint32_t a;
    asm("{ .reg .u64 t; cvta.to.shared.u64 t, %1; cvt.u32.u64 %0, t; }" : "=r"(a) : "l"(p));
    return a;
}
#define CPA(sa, gp) asm volatile("cp.async.cg.shared.global [%0], [%1], 16;" :: "r"(sa), "l"(gp))
#define CPC()  asm volatile("cp.async.commit_group;" ::: "memory")
#define CPW(n) asm volatile("cp.async.wait_group %0;" :: "n"(n) : "memory")

__device__ __forceinline__ void mma16(float* d, const uint32_t* a, uint32_t b0, uint32_t b1) {
    asm volatile(
        "mma.sync.aligned.m16n8k16.row.col.f32.f16.f16.f32 "
        "{%0,%1,%2,%3}, {%4,%5,%6,%7}, {%8,%9}, {%0,%1,%2,%3};"
        : "+f"(d[0]), "+f"(d[1]), "+f"(d[2]), "+f"(d[3])
        : "r"(a[0]), "r"(a[1]), "r"(a[2]), "r"(a[3]), "r"(b0), "r"(b1));
}
#define LDSM4(r0, r1, r2, r3, addr)                                            \
    asm volatile("ldmatrix.sync.aligned.m8n8.x4.shared.b16 {%0,%1,%2,%3}, [%4];" \
        : "=r"(r0), "=r"(r1), "=r"(r2), "=r"(r3) : "r"(addr))
#define LDSM4T(r0, r1, r2, r3, addr)                                           \
    asm volatile("ldmatrix.sync.aligned.m8n8.x4.trans.shared.b16 {%0,%1,%2,%3}, [%4];" \
        : "=r"(r0), "=r"(r1), "=r"(r2), "=r"(r3) : "r"(addr))

// Inputs already carry the 0.5 factor (folded into Q projection):
// P = 0.5*tanh(S_half) + 0.5 where S_half = 0.5*S_orig.
__device__ __forceinline__ uint32_t sig2(float lo, float hi) {
    __half2 v = __floats2half2_rn(lo, hi);
    uint32_t u = *reinterpret_cast<uint32_t*>(&v);
    uint32_t t;
    asm("tanh.approx.f16x2 %0, %1;" : "=r"(t) : "r"(u));
    __half2 th = *reinterpret_cast<__half2*>(&t);
    __half2 hf = __floats2half2_rn(0.5f, 0.5f);
    __half2 r = __hfma2(th, hf, hf);
    return *reinterpret_cast<uint32_t*>(&r);
}

// ---------------------------------------------------------------------------
// prep: x (f32) -> g_V (fp16) ; Wq,Wk (f32) -> g_Wq,g_Wk (fp16)
// ---------------------------------------------------------------------------
#define NX  (M_ROWS * DIM / 4)
#define NW  (DIM * DIM / 4)
__global__ __launch_bounds__(256) void prep(const float* __restrict__ x,
                                            const float* __restrict__ Wq,
                                            const float* __restrict__ Wk) {
    const int i = blockIdx.x * 256 + threadIdx.x;
    const float* src;
    __half* dst;
    int j;
    if (i < NX)             { src = x;  dst = g_V;  j = i; }
    else if (i < NX + NW)   { src = Wq; dst = g_Wq; j = i - NX; }
    else                    { src = Wk; dst = g_Wk; j = i - NX - NW; }
    float4 v = reinterpret_cast<const float4*>(src)[j];
    __half2 h0 = __floats2half2_rn(v.x, v.y);
    __half2 h1 = __floats2half2_rn(v.z, v.w);
    uint2 u;
    u.x = *reinterpret_cast<uint32_t*>(&h0);
    u.y = *reinterpret_cast<uint32_t*>(&h1);
    reinterpret_cast<uint2*>(dst)[j] = u;
}

// ---------------------------------------------------------------------------
// Projection, fp16 mma + ldmatrix. Q epilogue folds the tanh 0.5 factor:
// g_Q = h((x@Wq)*SCALE*0.5 + 0.5*bias), g_K = h(x@Wk)
// ---------------------------------------------------------------------------
#define P2_AS 72
#define P2_BS 136
#define P2_A_SZ (128 * P2_AS)
#define P2_B_SZ (64 * P2_BS)
#define P2_SMEM ((2 * P2_A_SZ + 2 * P2_B_SZ) * 2)

__global__ __launch_bounds__(256) void proj_tc(const float* __restrict__ bias)
{
    extern __shared__ __half smh[];
    const uint32_t sb = su32(smh);
    const uint32_t sA = sb;
    const uint32_t sB = sb + (uint32_t)(2 * P2_A_SZ) * 2u;

    const int which = blockIdx.z;
    const __half* W = which ? g_Wk : g_Wq;
    __half* outp = which ? g_K : g_Q;

    const int tid = threadIdx.x;
    const int wid = tid >> 5, lane = tid & 31;
    const int g = lane >> 2, t = lane & 3;
    const int rg = wid >> 1, cg = wid & 1;
    const int row0 = blockIdx.y * 128, col0 = blockIdx.x * 128;

    const int lq = lane >> 3, lr = lane & 7;
    const int a_row = ((lq >> 1) << 3) + lr;
    const int a_col = (lq & 1) << 3;
    const int b_row = ((lq & 1) << 3) + lr;
    const int b_col = (lq >> 1) << 3;

    #define P2_LOAD(kt, buf) do {                                               \
        const __half* _sa = g_V + (size_t)row0 * DIM + (kt) * 64;               \
        uint32_t _da = sA + (uint32_t)((buf) * P2_A_SZ) * 2u;                   \
        _Pragma("unroll")                                                       \
        for (int i = 0; i < 4; i++) {                                           \
            int c = tid + i * 256, r = c >> 3, c8 = (c & 7) << 3;               \
            CPA(_da + (uint32_t)(r * P2_AS + c8) * 2u, _sa + (size_t)r * DIM + c8); \
        }                                                                       \
        const __half* _sb = W + (size_t)((kt) * 64) * DIM + col0;               \
        uint32_t _db = sB + (uint32_t)((buf) * P2_B_SZ) * 2u;                   \
        _Pragma("unroll")                                                       \
        for (int i = 0; i < 4; i++) {                                           \
            int c = tid + i * 256, r = c >> 4, c8 = (c & 15) << 3;              \
            CPA(_db + (uint32_t)(r * P2_BS + c8) * 2u, _sb + (size_t)r * DIM + c8); \
        }                                                                       \
        CPC();                                                                  \
    } while (0)

    float C[2][8][4] = {};

    P2_LOAD(0, 0);
    for (int kt = 0; kt < 8; kt++) {
        const int buf = kt & 1;
        if (kt < 7) { P2_LOAD(kt + 1, buf ^ 1); CPW(1); } else { CPW(0); }
        __syncthreads();
        const uint32_t Ab = sA + (uint32_t)(buf * P2_A_SZ) * 2u;
        const uint32_t Bb = sB + (uint32_t)(buf * P2_B_SZ) * 2u;
#pragma unroll
        for (int kb = 0; kb < 4; kb++) {
            const int k0 = kb * 16;
            uint32_t af[2][4];
#pragma unroll
            for (int f = 0; f < 2; f++) {
                uint32_t r0, r1, r2, r3;
                LDSM4(r0, r1, r2, r3,
                      Ab + (uint32_t)((rg * 32 + f * 16 + a_row) * P2_AS + k0 + a_col) * 2u);
                af[f][0] = r0; af[f][1] = r2; af[f][2] = r1; af[f][3] = r3;
            }
#pragma unroll
            for (int nf2 = 0; nf2 < 4; nf2++) {
                uint32_t r0, r1, r2, r3;
                LDSM4T(r0, r1, r2, r3,
                       Bb + (uint32_t)((k0 + b_row) * P2_BS + cg * 64 + nf2 * 16 + b_col) * 2u);
                mma16(C[0][2 * nf2],     af[0], r0, r1);
                mma16(C[0][2 * nf2 + 1], af[0], r2, r3);
                mma16(C[1][2 * nf2],     af[1], r0, r1);
                mma16(C[1][2 * nf2 + 1], af[1], r2, r3);
            }
        }
        __syncthreads();
    }

#pragma unroll
    for (int f = 0; f < 2; f++) {
        const int r = row0 + rg * 32 + f * 16 + g;
#pragma unroll
        for (int cf = 0; cf < 8; cf++) {
            const int cb = col0 + cg * 64 + cf * 8 + 2 * t;
            float v0 = C[f][cf][0], v1 = C[f][cf][1], v2 = C[f][cf][2], v3 = C[f][cf][3];
            if (which == 0) {
                const float hs = 0.5f * SCALE;
                v0 = v0 * hs + 0.5f * bias[cb];     v1 = v1 * hs + 0.5f * bias[cb + 1];
                v2 = v2 * hs + 0.5f * bias[cb];     v3 = v3 * hs + 0.5f * bias[cb + 1];
            }
            *(__half2*)&outp[(size_t)r * DIM + cb]       = __floats2half2_rn(v0, v1);
            *(__half2*)&outp[(size_t)(r + 8) * DIM + cb] = __floats2half2_rn(v2, v3);
        }
    }
}

// ---------------------------------------------------------------------------
// Fused sigmoid attention: 4 warps x 32 Q-rows, ring-6 smem buffers,
// ONE __syncthreads per 2 key tiles -> warps drift a full jt to overlap
// MUFU (sigmoid) with other warps' HMMA. Prefetch distance 2 tiles.
// smem: (6 K + 6 V) x [64][72] halves = 110,592 B -> 2 CTAs/SM.
// ---------------------------------------------------------------------------
#define KT  64
#define NT  (N_SEQ / KT)
#define KS  72
#define K_BUF (KT * KS)
#define VOFF0 (6 * K_BUF)
#define AT_SMEM (12 * K_BUF * 2)

__global__ __launch_bounds__(128, 2) void attn_tc(float* __restrict__ out)
{
    extern __shared__ __half smh[];
    const uint32_t sb = su32(smh);
    const int tid = threadIdx.x;
    const int wid = tid >> 5, lane = tid & 31;
    const int g = lane >> 2, t = lane & 3;

    const int it = blockIdx.x, h = blockIdx.y, b = blockIdx.z;
    const size_t base = (size_t)b * N_SEQ * DIM + (size_t)h * DK;
    const __half* qgm = g_Q + base + (size_t)(it * 128) * DIM;
    const __half* kgm = g_K + base;
    const __half* vgm = g_V + base;

    const int lq = lane >> 3, lr = lane & 7;
    const int k_row = ((lq >> 1) << 3) + lr;
    const int k_col = (lq & 1) << 3;
    const int v_row = ((lq & 1) << 3) + lr;
    const int v_col = (lq >> 1) << 3;

    // Q fragments for 2 strips (rows wid*32 + s*16 + g / +8)
    uint32_t qf[2][4][4];
#pragma unroll
    for (int s = 0; s < 2; s++) {
        const __half* q0 = qgm + (size_t)(wid * 32 + s * 16 + g) * DIM;
        const __half* q1 = q0 + (size_t)8 * DIM;
#pragma unroll
        for (int kb = 0; kb < 4; kb++) {
            qf[s][kb][0] = *(const uint32_t*)(q0 + 16 * kb + 2 * t);
            qf[s][kb][1] = *(const uint32_t*)(q1 + 16 * kb + 2 * t);
            qf[s][kb][2] = *(const uint32_t*)(q0 + 16 * kb + 8 + 2 * t);
            qf[s][kb][3] = *(const uint32_t*)(q1 + 16 * kb + 8 + 2 * t);
        }
    }

    // Load ONE tile (K+V) into ring slot; caller groups two tiles per commit.
    #define LOAD_ONE(jt_) do {                                                  \
        const int _buf = (jt_) % 6;                                             \
        const __half* _ks = kgm + (size_t)((jt_) * KT) * DIM;                   \
        const __half* _vs = vgm + (size_t)((jt_) * KT) * DIM;                   \
        uint32_t _kd = sb + (uint32_t)(_buf * K_BUF) * 2u;                      \
        uint32_t _vd = sb + (uint32_t)(VOFF0 + _buf * K_BUF) * 2u;              \
        _Pragma("unroll")                                                       \
        for (int i = 0; i < 4; i++) {                                           \
            int c = tid + i * 128, r = c >> 3, c8 = (c & 7) << 3;               \
            CPA(_kd + (uint32_t)(r * KS + c8) * 2u, _ks + (size_t)r * DIM + c8);\
            CPA(_vd + (uint32_t)(r * KS + c8) * 2u, _vs + (size_t)r * DIM + c8);\
        }                                                                       \
    } while (0)
    #define LOAD2(jt_) do { LOAD_ONE(jt_); LOAD_ONE((jt_) + 1); CPC(); } while (0)

    float O[2][8][4] = {};

    LOAD2(0);            // tiles 0,1 -> bufs 0,1
    LOAD2(2);            // tiles 2,3 -> bufs 2,3

    for (int jt2 = 0; jt2 < NT; jt2 += 2) {
        if (jt2 + 2 >= NT) { CPW(0); } else { CPW(1); }   // tiles jt2,jt2+1 landed
        __syncthreads();   // all warps released bufs (jt2+4)%6,(jt2+5)%6
        if (jt2 + 4 < NT) LOAD2(jt2 + 4);

#pragma unroll
        for (int j = 0; j < 2; j++) {
            const int jt = jt2 + j;
            const int buf = jt % 6;
            const uint32_t ksb = sb + (uint32_t)(buf * K_BUF) * 2u;
            const uint32_t vsb = sb + (uint32_t)((VOFF0 + buf * K_BUF)) * 2u;

            // ---- GEMM1: S(32x64) = Q K^T ----
            float S[2][8][4] = {};
#pragma unroll
            for (int kb = 0; kb < 4; kb++) {
                const int k0 = kb * 16;
#pragma unroll
                for (int nf2 = 0; nf2 < 4; nf2++) {
                    const int n0 = nf2 * 16;
                    uint32_t r0, r1, r2, r3;
                    LDSM4(r0, r1, r2, r3,
                          ksb + (uint32_t)((n0 + k_row) * KS + k0 + k_col) * 2u);
#pragma unroll
                    for (int s = 0; s < 2; s++) {
                        mma16(S[s][2 * nf2],     qf[s][kb], r0, r1);
                        mma16(S[s][2 * nf2 + 1], qf[s][kb], r2, r3);
                    }
                }
            }

            // ---- P = f16x2 sigmoid (0.5 pre-folded into Q) ----
            uint32_t pa[2][4][4];
#pragma unroll
            for (int s = 0; s < 2; s++)
#pragma unroll
                for (int kt = 0; kt < 4; kt++) {
                    pa[s][kt][0] = sig2(S[s][2 * kt][0],     S[s][2 * kt][1]);
                    pa[s][kt][1] = sig2(S[s][2 * kt][2],     S[s][2 * kt][3]);
                    pa[s][kt][2] = sig2(S[s][2 * kt + 1][0], S[s][2 * kt + 1][1]);
                    pa[s][kt][3] = sig2(S[s][2 * kt + 1][2], S[s][2 * kt + 1][3]);
                }

            // ---- GEMM2: O(32x64) += P V ----
#pragma unroll
            for (int kt = 0; kt < 4; kt++) {
                const int k0 = kt * 16;
#pragma unroll
                for (int nf2 = 0; nf2 < 4; nf2++) {
                    const int n0 = nf2 * 16;
                    uint32_t r0, r1, r2, r3;
                    LDSM4T(r0, r1, r2, r3,
                           vsb + (uint32_t)((k0 + v_row) * KS + n0 + v_col) * 2u);
#pragma unroll
                    for (int s = 0; s < 2; s++) {
                        mma16(O[s][2 * nf2],     pa[s][kt], r0, r1);
                        mma16(O[s][2 * nf2 + 1], pa[s][kt], r2, r3);
                    }
                }
            }
        }
    }

    // ---- epilogue ----
#pragma unroll
    for (int s = 0; s < 2; s++) {
        const int r0 = it * 128 + wid * 32 + s * 16 + g;
        float* og = out + ((size_t)b * N_SEQ + r0) * DIM + h * DK;
#pragma unroll
        for (int nf = 0; nf < 8; nf++) {
            const int d = nf * 8 + 2 * t;
            *(float2*)&og[d] = make_float2(O[s][nf][0], O[s][nf][1]);
            *(float2*)(og + (size_t)8 * DIM + d) = make_float2(O[s][nf][2], O[s][nf][3]);
        }
    }
}

extern "C" void kernel_launch(void* const* d_in, const int* in_sizes, int n_in,
                              void* d_out, int out_size)
{
    const float* x    = (const float*)d_in[0];
    const float* Wq   = (const float*)d_in[1];
    const float* Wk   = (const float*)d_in[2];
    const float* bias = (const float*)d_in[3];
    float* out = (float*)d_out;

    cudaFuncSetAttribute(proj_tc, cudaFuncAttributeMaxDynamicSharedMemorySize, P2_SMEM);
    cudaFuncSetAttribute(attn_tc, cudaFuncAttributeMaxDynamicSharedMemorySize, AT_SMEM);

    prep<<<(NX + 2 * NW + 255) / 256, 256>>>(x, Wq, Wk);
    proj_tc<<<dim3(DIM / 128, M_ROWS / 128, 2), 256, P2_SMEM>>>(bias);
    attn_tc<<<dim3(N_SEQ / 128, NH, B_SZ), 128, AT_SMEM>>>(out);
}

// round 10
// speedup vs baseline: 8.4506x; 1.0013x over previous
#include <cuda_runtime.h>
#include <cuda_fp16.h>
#include <cstdint>

#define B_SZ  4
#define N_SEQ 2048
#define DIM   512
#define NH    8
#define DK    64
#define M_ROWS (B_SZ * N_SEQ)
#define SCALE 0.125f

// Scratch: projected Q (pre-scaled for tanh-sigmoid), K, V (= x), fp16 weights.
__device__ __half g_Q[M_ROWS * DIM];
__device__ __half g_K[M_ROWS * DIM];
__device__ __half g_V[M_ROWS * DIM];
__device__ __half g_Wq[DIM * DIM];
__device__ __half g_Wk[DIM * DIM];

// ---------------------------------------------------------------------------
// helpers (portable PTX, sm_80-class only)
// ---------------------------------------------------------------------------
__device__ __forceinline__ uint32_t su32(const void* p) {
    uint32_t a;
    asm("{ .reg .u64 t; cvta.to.shared.u64 t, %1; cvt.u32.u64 %0, t; }" : "=r"(a) : "l"(p));
    return a;
}
#define CPA(sa, gp) asm volatile("cp.async.cg.shared.global [%0], [%1], 16;" :: "r"(sa), "l"(gp))
#define CPC()  asm volatile("cp.async.commit_group;" ::: "memory")
#define CPW(n) asm volatile("cp.async.wait_group %0;" :: "n"(n) : "memory")

__device__ __forceinline__ void mma16(float* d, const uint32_t* a, uint32_t b0, uint32_t b1) {
    asm volatile(
        "mma.sync.aligned.m16n8k16.row.col.f32.f16.f16.f32 "
        "{%0,%1,%2,%3}, {%4,%5,%6,%7}, {%8,%9}, {%0,%1,%2,%3};"
        : "+f"(d[0]), "+f"(d[1]), "+f"(d[2]), "+f"(d[3])
        : "r"(a[0]), "r"(a[1]), "r"(a[2]), "r"(a[3]), "r"(b0), "r"(b1));
}
#define LDSM4(r0, r1, r2, r3, addr)                                            \
    asm volatile("ldmatrix.sync.aligned.m8n8.x4.shared.b16 {%0,%1,%2,%3}, [%4];" \
        : "=r"(r0), "=r"(r1), "=r"(r2), "=r"(r3) : "r"(addr))
#define LDSM4T(r0, r1, r2, r3, addr)                                           \
    asm volatile("ldmatrix.sync.aligned.m8n8.x4.trans.shared.b16 {%0,%1,%2,%3}, [%4];" \
        : "=r"(r0), "=r"(r1), "=r"(r2), "=r"(r3) : "r"(addr))

// Inputs already carry the 0.5 factor (folded into Q projection):
// P = 0.5*tanh(S_half) + 0.5 where S_half = 0.5*S_orig.
__device__ __forceinline__ uint32_t sig2(float lo, float hi) {
    __half2 v = __floats2half2_rn(lo, hi);
    uint32_t u = *reinterpret_cast<uint32_t*>(&v);
    uint32_t t;
    asm("tanh.approx.f16x2 %0, %1;" : "=r"(t) : "r"(u));
    __half2 th = *reinterpret_cast<__half2*>(&t);
    __half2 hf = __floats2half2_rn(0.5f, 0.5f);
    __half2 r = __hfma2(th, hf, hf);
    return *reinterpret_cast<uint32_t*>(&r);
}

// ---------------------------------------------------------------------------
// prep: x (f32) -> g_V (fp16) ; Wq,Wk (f32) -> g_Wq,g_Wk (fp16)
// ---------------------------------------------------------------------------
#define NX  (M_ROWS * DIM / 4)
#define NW  (DIM * DIM / 4)
__global__ __launch_bounds__(256) void prep(const float* __restrict__ x,
                                            const float* __restrict__ Wq,
                                            const float* __restrict__ Wk) {
    const int i = blockIdx.x * 256 + threadIdx.x;
    const float* src;
    __half* dst;
    int j;
    if (i < NX)             { src = x;  dst = g_V;  j = i; }
    else if (i < NX + NW)   { src = Wq; dst = g_Wq; j = i - NX; }
    else                    { src = Wk; dst = g_Wk; j = i - NX - NW; }
    float4 v = reinterpret_cast<const float4*>(src)[j];
    __half2 h0 = __floats2half2_rn(v.x, v.y);
    __half2 h1 = __floats2half2_rn(v.z, v.w);
    uint2 u;
    u.x = *reinterpret_cast<uint32_t*>(&h0);
    u.y = *reinterpret_cast<uint32_t*>(&h1);
    reinterpret_cast<uint2*>(dst)[j] = u;
}

// ---------------------------------------------------------------------------
// Projection, fp16 mma + ldmatrix. Q epilogue folds the tanh 0.5 factor:
// g_Q = h((x@Wq)*SCALE*0.5 + 0.5*bias), g_K = h(x@Wk)
// ---------------------------------------------------------------------------
#define P2_AS 72
#define P2_BS 136
#define P2_A_SZ (128 * P2_AS)
#define P2_B_SZ (64 * P2_BS)
#define P2_SMEM ((2 * P2_A_SZ + 2 * P2_B_SZ) * 2)

__global__ __launch_bounds__(256) void proj_tc(const float* __restrict__ bias)
{
    extern __shared__ __half smh[];
    const uint32_t sb = su32(smh);
    const uint32_t sA = sb;
    const uint32_t sB = sb + (uint32_t)(2 * P2_A_SZ) * 2u;

    const int which = blockIdx.z;
    const __half* W = which ? g_Wk : g_Wq;
    __half* outp = which ? g_K : g_Q;

    const int tid = threadIdx.x;
    const int wid = tid >> 5, lane = tid & 31;
    const int g = lane >> 2, t = lane & 3;
    const int rg = wid >> 1, cg = wid & 1;
    const int row0 = blockIdx.y * 128, col0 = blockIdx.x * 128;

    const int lq = lane >> 3, lr = lane & 7;
    const int a_row = ((lq >> 1) << 3) + lr;
    const int a_col = (lq & 1) << 3;
    const int b_row = ((lq & 1) << 3) + lr;
    const int b_col = (lq >> 1) << 3;

    #define P2_LOAD(kt, buf) do {                                               \
        const __half* _sa = g_V + (size_t)row0 * DIM + (kt) * 64;               \
        uint32_t _da = sA + (uint32_t)((buf) * P2_A_SZ) * 2u;                   \
        _Pragma("unroll")                                                       \
        for (int i = 0; i < 4; i++) {                                           \
            int c = tid + i * 256, r = c >> 3, c8 = (c & 7) << 3;               \
            CPA(_da + (uint32_t)(r * P2_AS + c8) * 2u, _sa + (size_t)r * DIM + c8); \
        }                                                                       \
        const __half* _sb = W + (size_t)((kt) * 64) * DIM + col0;               \
        uint32_t _db = sB + (uint32_t)((buf) * P2_B_SZ) * 2u;                   \
        _Pragma("unroll")                                                       \
        for (int i = 0; i < 4; i++) {                                           \
            int c = tid + i * 256, r = c >> 4, c8 = (c & 15) << 3;              \
            CPA(_db + (uint32_t)(r * P2_BS + c8) * 2u, _sb + (size_t)r * DIM + c8); \
        }                                                                       \
        CPC();                                                                  \
    } while (0)

    float C[2][8][4] = {};

    P2_LOAD(0, 0);
    for (int kt = 0; kt < 8; kt++) {
        const int buf = kt & 1;
        if (kt < 7) { P2_LOAD(kt + 1, buf ^ 1); CPW(1); } else { CPW(0); }
        __syncthreads();
        const uint32_t Ab = sA + (uint32_t)(buf * P2_A_SZ) * 2u;
        const uint32_t Bb = sB + (uint32_t)(buf * P2_B_SZ) * 2u;
#pragma unroll
        for (int kb = 0; kb < 4; kb++) {
            const int k0 = kb * 16;
            uint32_t af[2][4];
#pragma unroll
            for (int f = 0; f < 2; f++) {
                uint32_t r0, r1, r2, r3;
                LDSM4(r0, r1, r2, r3,
                      Ab + (uint32_t)((rg * 32 + f * 16 + a_row) * P2_AS + k0 + a_col) * 2u);
                af[f][0] = r0; af[f][1] = r2; af[f][2] = r1; af[f][3] = r3;
            }
#pragma unroll
            for (int nf2 = 0; nf2 < 4; nf2++) {
                uint32_t r0, r1, r2, r3;
                LDSM4T(r0, r1, r2, r3,
                       Bb + (uint32_t)((k0 + b_row) * P2_BS + cg * 64 + nf2 * 16 + b_col) * 2u);
                mma16(C[0][2 * nf2],     af[0], r0, r1);
                mma16(C[0][2 * nf2 + 1], af[0], r2, r3);
                mma16(C[1][2 * nf2],     af[1], r0, r1);
                mma16(C[1][2 * nf2 + 1], af[1], r2, r3);
            }
        }
        __syncthreads();
    }

#pragma unroll
    for (int f = 0; f < 2; f++) {
        const int r = row0 + rg * 32 + f * 16 + g;
#pragma unroll
        for (int cf = 0; cf < 8; cf++) {
            const int cb = col0 + cg * 64 + cf * 8 + 2 * t;
            float v0 = C[f][cf][0], v1 = C[f][cf][1], v2 = C[f][cf][2], v3 = C[f][cf][3];
            if (which == 0) {
                const float hs = 0.5f * SCALE;
                v0 = v0 * hs + 0.5f * bias[cb];     v1 = v1 * hs + 0.5f * bias[cb + 1];
                v2 = v2 * hs + 0.5f * bias[cb];     v3 = v3 * hs + 0.5f * bias[cb + 1];
            }
            *(__half2*)&outp[(size_t)r * DIM + cb]       = __floats2half2_rn(v0, v1);
            *(__half2*)&outp[(size_t)(r + 8) * DIM + cb] = __floats2half2_rn(v2, v3);
        }
    }
}

// ---------------------------------------------------------------------------
// Fused sigmoid attention: 4 warps x 32 Q-rows, register-lean per-16-key-block
// pipeline (GEMM1 block -> sigmoid -> GEMM2 block), ring-4 smem buffers,
// 3 CTAs/SM (12 warps) for LDSM-latency coverage. Sync per 2 key tiles.
// smem: (4 K + 4 V) x [64][72] halves = 73,728 B -> 3 CTAs/SM = 221,184 B.
// ---------------------------------------------------------------------------
#define KT  64
#define NT  (N_SEQ / KT)
#define KS  72
#define K_BUF (KT * KS)
#define VOFF0 (4 * K_BUF)
#define AT_SMEM (8 * K_BUF * 2)

__global__ __launch_bounds__(128, 3) void attn_tc(float* __restrict__ out)
{
    extern __shared__ __half smh[];
    const uint32_t sb = su32(smh);
    const int tid = threadIdx.x;
    const int wid = tid >> 5, lane = tid & 31;
    const int g = lane >> 2, t = lane & 3;

    const int it = blockIdx.x, h = blockIdx.y, b = blockIdx.z;
    const size_t base = (size_t)b * N_SEQ * DIM + (size_t)h * DK;
    const __half* qgm = g_Q + base + (size_t)(it * 128) * DIM;
    const __half* kgm = g_K + base;
    const __half* vgm = g_V + base;

    const int lq = lane >> 3, lr = lane & 7;
    const int k_row = ((lq >> 1) << 3) + lr;
    const int k_col = (lq & 1) << 3;
    const int v_row = ((lq & 1) << 3) + lr;
    const int v_col = (lq >> 1) << 3;

    // Q fragments for 2 strips (rows wid*32 + s*16 + g / +8)
    uint32_t qf[2][4][4];
#pragma unroll
    for (int s = 0; s < 2; s++) {
        const __half* q0 = qgm + (size_t)(wid * 32 + s * 16 + g) * DIM;
        const __half* q1 = q0 + (size_t)8 * DIM;
#pragma unroll
        for (int kb = 0; kb < 4; kb++) {
            qf[s][kb][0] = *(const uint32_t*)(q0 + 16 * kb + 2 * t);
            qf[s][kb][1] = *(const uint32_t*)(q1 + 16 * kb + 2 * t);
            qf[s][kb][2] = *(const uint32_t*)(q0 + 16 * kb + 8 + 2 * t);
            qf[s][kb][3] = *(const uint32_t*)(q1 + 16 * kb + 8 + 2 * t);
        }
    }

    #define LOAD_ONE(jt_) do {                                                  \
        const int _buf = (jt_) & 3;                                             \
        const __half* _ks = kgm + (size_t)((jt_) * KT) * DIM;                   \
        const __half* _vs = vgm + (size_t)((jt_) * KT) * DIM;                   \
        uint32_t _kd = sb + (uint32_t)(_buf * K_BUF) * 2u;                      \
        uint32_t _vd = sb + (uint32_t)(VOFF0 + _buf * K_BUF) * 2u;              \
        _Pragma("unroll")                                                       \
        for (int i = 0; i < 4; i++) {                                           \
            int c = tid + i * 128, r = c >> 3, c8 = (c & 7) << 3;               \
            CPA(_kd + (uint32_t)(r * KS + c8) * 2u, _ks + (size_t)r * DIM + c8);\
            CPA(_vd + (uint32_t)(r * KS + c8) * 2u, _vs + (size_t)r * DIM + c8);\
        }                                                                       \
    } while (0)
    #define LOAD2(jt_) do { LOAD_ONE(jt_); LOAD_ONE((jt_) + 1); CPC(); } while (0)

    float O[2][8][4] = {};

    LOAD2(0);   // tiles 0,1 -> slots 0,1

    for (int jt2 = 0; jt2 < NT; jt2 += 2) {
        CPW(0);            // tiles jt2, jt2+1 landed
        __syncthreads();   // all warps done with tiles jt2-2, jt2-1 (slots (jt2+2)&3,(jt2+3)&3)
        if (jt2 + 2 < NT) LOAD2(jt2 + 2);

#pragma unroll
        for (int j = 0; j < 2; j++) {
            const int jt = jt2 + j;
            const int buf = jt & 3;
            const uint32_t ksb = sb + (uint32_t)(buf * K_BUF) * 2u;
            const uint32_t vsb = sb + (uint32_t)((VOFF0 + buf * K_BUF)) * 2u;

            // per 16-key block: GEMM1 -> sigmoid -> GEMM2 (S live range = 16 regs)
#pragma unroll
            for (int nf2 = 0; nf2 < 4; nf2++) {
                const int n0 = nf2 * 16;

                // ---- GEMM1 block: Sb(32x16) = Q K^T ----
                float Sb[2][2][4] = {};
#pragma unroll
                for (int kb = 0; kb < 4; kb++) {
                    const int k0 = kb * 16;
                    uint32_t r0, r1, r2, r3;
                    LDSM4(r0, r1, r2, r3,
                          ksb + (uint32_t)((n0 + k_row) * KS + k0 + k_col) * 2u);
#pragma unroll
                    for (int s = 0; s < 2; s++) {
                        mma16(Sb[s][0], qf[s][kb], r0, r1);
                        mma16(Sb[s][1], qf[s][kb], r2, r3);
                    }
                }

                // ---- sigmoid -> A-fragment (0.5 pre-folded into Q) ----
                uint32_t pb[2][4];
#pragma unroll
                for (int s = 0; s < 2; s++) {
                    pb[s][0] = sig2(Sb[s][0][0], Sb[s][0][1]);
                    pb[s][1] = sig2(Sb[s][0][2], Sb[s][0][3]);
                    pb[s][2] = sig2(Sb[s][1][0], Sb[s][1][1]);
                    pb[s][3] = sig2(Sb[s][1][2], Sb[s][1][3]);
                }

                // ---- GEMM2 block: O(32x64) += P(:,n0:n0+16) V(n0:n0+16,:) ----
#pragma unroll
                for (int nv = 0; nv < 4; nv++) {
                    const int n0v = nv * 16;
                    uint32_t r0, r1, r2, r3;
                    LDSM4T(r0, r1, r2, r3,
                           vsb + (uint32_t)((n0 + v_row) * KS + n0v + v_col) * 2u);
#pragma unroll
                    for (int s = 0; s < 2; s++) {
                        mma16(O[s][2 * nv],     pb[s], r0, r1);
                        mma16(O[s][2 * nv + 1], pb[s], r2, r3);
                    }
                }
            }
        }
    }

    // ---- epilogue ----
#pragma unroll
    for (int s = 0; s < 2; s++) {
        const int r0 = it * 128 + wid * 32 + s * 16 + g;
        float* og = out + ((size_t)b * N_SEQ + r0) * DIM + h * DK;
#pragma unroll
        for (int nf = 0; nf < 8; nf++) {
            const int d = nf * 8 + 2 * t;
            *(float2*)&og[d] = make_float2(O[s][nf][0], O[s][nf][1]);
            *(float2*)(og + (size_t)8 * DIM + d) = make_float2(O[s][nf][2], O[s][nf][3]);
        }
    }
}

extern "C" void kernel_launch(void* const* d_in, const int* in_sizes, int n_in,
                              void* d_out, int out_size)
{
    const float* x    = (const float*)d_in[0];
    const float* Wq   = (const float*)d_in[1];
    const float* Wk   = (const float*)d_in[2];
    const float* bias = (const float*)d_in[3];
    float* out = (float*)d_out;

    cudaFuncSetAttribute(proj_tc, cudaFuncAttributeMaxDynamicSharedMemorySize, P2_SMEM);
    cudaFuncSetAttribute(attn_tc, cudaFuncAttributeMaxDynamicSharedMemorySize, AT_SMEM);

    prep<<<(NX + 2 * NW + 255) / 256, 256>>>(x, Wq, Wk);
    proj_tc<<<dim3(DIM / 128, M_ROWS / 128, 2), 256, P2_SMEM>>>(bias);
    attn_tc<<<dim3(N_SEQ / 128, NH, B_SZ), 128, AT_SMEM>>>(out);
}